// round 1
// baseline (speedup 1.0000x reference)
#include <cuda_runtime.h>
#include <cstdint>

#define BB 4
#define SS 1024
#define DD 1024
#define HH 16
#define HD 64
#define NEGV -10000000.0f

// Scratch (allocation-free rule: __device__ globals)
__device__ float g_q[BB*HH*SS*HD];
__device__ float g_k[BB*HH*SS*HD];
__device__ float g_v[BB*HH*SS*HD];
__device__ unsigned g_mask[BB*SS*(SS/32)];

// ---------------------------------------------------------------------------
// QKV GEMM: out[b,h,s,hd] = sum_k x[b,s,k]*W[k, h*64+hd] + bias
// blockIdx.z selects Q/K/V. Tile 64x64x16, 256 threads, 4x4 per thread.
// ---------------------------------------------------------------------------
#define BM 64
#define BN 64
#define BK 16

__global__ __launch_bounds__(256) void qkv_gemm(
    const float* __restrict__ x,
    const float* __restrict__ Wq, const float* __restrict__ bq,
    const float* __restrict__ Wk, const float* __restrict__ bk,
    const float* __restrict__ Wv, const float* __restrict__ bv)
{
    const float* W; const float* bias; float* out;
    if (blockIdx.z == 0)      { W = Wq; bias = bq; out = g_q; }
    else if (blockIdx.z == 1) { W = Wk; bias = bk; out = g_k; }
    else                      { W = Wv; bias = bv; out = g_v; }

    __shared__ float As[BK][BM + 4];   // x tile, transposed: As[k][m]
    __shared__ float Bs[BK][BN];       // W tile, natural:    Bs[k][n]

    const int tid = threadIdx.x;
    const int tx  = tid & 15;          // 16 col-groups
    const int ty  = tid >> 4;          // 16 row-groups
    const int m0  = blockIdx.y * BM;
    const int n0  = blockIdx.x * BN;   // == head * 64

    float acc[4][4];
    #pragma unroll
    for (int i = 0; i < 4; i++)
        #pragma unroll
        for (int j = 0; j < 4; j++) acc[i][j] = 0.f;

    const int lr = tid >> 2;           // x load: row 0..63
    const int lc = (tid & 3) * 4;      // x load: col 0..12
    const int wr = tid >> 4;           // W load: row 0..15
    const int wc = (tid & 15) * 4;     // W load: col 0..60

    for (int k0 = 0; k0 < DD; k0 += BK) {
        float4 xv = *(const float4*)(x + (size_t)(m0 + lr) * DD + k0 + lc);
        float4 wv = *(const float4*)(W + (size_t)(k0 + wr) * DD + n0 + wc);
        __syncthreads();
        As[lc + 0][lr] = xv.x;
        As[lc + 1][lr] = xv.y;
        As[lc + 2][lr] = xv.z;
        As[lc + 3][lr] = xv.w;
        *(float4*)&Bs[wr][wc] = wv;
        __syncthreads();
        #pragma unroll
        for (int kk = 0; kk < BK; kk++) {
            float a[4], b[4];
            *(float4*)a = *(float4*)&As[kk][ty * 4];
            *(float4*)b = *(float4*)&Bs[kk][tx * 4];
            #pragma unroll
            for (int i = 0; i < 4; i++)
                #pragma unroll
                for (int j = 0; j < 4; j++)
                    acc[i][j] += a[i] * b[j];
        }
    }

    const int h   = blockIdx.x;        // BN==64 -> one head per tile
    const int hd0 = tx * 4;
    float4 b4 = *(const float4*)(bias + n0 + hd0);
    #pragma unroll
    for (int i = 0; i < 4; i++) {
        int m = m0 + ty * 4 + i;
        int bb = m >> 10;
        int s  = m & 1023;
        float4 o;
        o.x = acc[i][0] + b4.x;
        o.y = acc[i][1] + b4.y;
        o.z = acc[i][2] + b4.z;
        o.w = acc[i][3] + b4.w;
        *(float4*)(out + ((size_t)(bb * HH + h) * SS + s) * HD + hd0) = o;
    }
}

// ---------------------------------------------------------------------------
// Pack adj into 1-bit mask (bit set => adj>=0.5 => no penalty) and copy adj
// into the second output region.
// ---------------------------------------------------------------------------
__global__ __launch_bounds__(256) void mask_pack(
    const float* __restrict__ adj, float* __restrict__ adj_out)
{
    int w = blockIdx.x * blockDim.x + threadIdx.x;   // 131072 words
    const float4* a4 = (const float4*)adj;
    float4* o4 = (float4*)adj_out;
    unsigned bits = 0;
    #pragma unroll
    for (int i = 0; i < 8; i++) {
        float4 v = a4[(size_t)w * 8 + i];
        o4[(size_t)w * 8 + i] = v;
        bits |= (v.x >= 0.5f ? 1u : 0u) << (i * 4 + 0);
        bits |= (v.y >= 0.5f ? 1u : 0u) << (i * 4 + 1);
        bits |= (v.z >= 0.5f ? 1u : 0u) << (i * 4 + 2);
        bits |= (v.w >= 0.5f ? 1u : 0u) << (i * 4 + 3);
    }
    g_mask[w] = bits;
}

// ---------------------------------------------------------------------------
// Flash attention (fp32): block = (q-tile 64, head, batch); 256 threads.
// Online softmax over 16 k-tiles of 64. relu fused in epilogue.
// ---------------------------------------------------------------------------
#define PAD 68

__global__ __launch_bounds__(256) void attn(float* __restrict__ out)
{
    extern __shared__ float sm[];
    float* Qts = sm;                 // [hd][qrow]  stride PAD (transposed)
    float* Kts = sm + 64 * PAD;      // [hd][kcol]  stride PAD (transposed)
    float* Vs  = sm + 2 * 64 * PAD;  // [kcol][hd]  stride PAD (natural)
    float* Ps  = sm + 3 * 64 * PAD;  // [qrow][kcol] stride PAD

    const int tid = threadIdx.x;
    const int tx  = tid & 15;
    const int ty  = tid >> 4;
    const int q0  = blockIdx.x * 64;
    const int h   = blockIdx.y;
    const int bb  = blockIdx.z;

    const float* qb = g_q + ((size_t)(bb * HH + h) * SS) * HD;
    const float* kb = g_k + ((size_t)(bb * HH + h) * SS) * HD;
    const float* vb = g_v + ((size_t)(bb * HH + h) * SS) * HD;

    // Load Q tile transposed
    #pragma unroll
    for (int i = 0; i < 4; i++) {
        int f   = tid + i * 256;
        int row = f >> 4;
        int c4  = (f & 15) * 4;
        float4 v = *(const float4*)(qb + (size_t)(q0 + row) * HD + c4);
        Qts[(c4 + 0) * PAD + row] = v.x;
        Qts[(c4 + 1) * PAD + row] = v.y;
        Qts[(c4 + 2) * PAD + row] = v.z;
        Qts[(c4 + 3) * PAD + row] = v.w;
    }

    float m_i[4], l_i[4], acc[4][4];
    #pragma unroll
    for (int i = 0; i < 4; i++) {
        m_i[i] = -1e30f; l_i[i] = 0.f;
        #pragma unroll
        for (int j = 0; j < 4; j++) acc[i][j] = 0.f;
    }

    const unsigned* mrow = g_mask + (size_t)bb * SS * (SS / 32);
    const int wsel = tx >> 3;            // which 32-bit word within 64-col tile
    const int bit0 = (tx & 7) * 4;

    for (int kt = 0; kt < 16; kt++) {
        __syncthreads();   // prev PV done before K/V overwrite
        #pragma unroll
        for (int i = 0; i < 4; i++) {
            int f   = tid + i * 256;
            int row = f >> 4;
            int c4  = (f & 15) * 4;
            float4 kv = *(const float4*)(kb + (size_t)(kt * 64 + row) * HD + c4);
            Kts[(c4 + 0) * PAD + row] = kv.x;
            Kts[(c4 + 1) * PAD + row] = kv.y;
            Kts[(c4 + 2) * PAD + row] = kv.z;
            Kts[(c4 + 3) * PAD + row] = kv.w;
            float4 vv = *(const float4*)(vb + (size_t)(kt * 64 + row) * HD + c4);
            *(float4*)&Vs[row * PAD + c4] = vv;
        }
        __syncthreads();

        // S = Q K^T (contraction over hd)
        float s[4][4];
        #pragma unroll
        for (int i = 0; i < 4; i++)
            #pragma unroll
            for (int j = 0; j < 4; j++) s[i][j] = 0.f;
        #pragma unroll 8
        for (int hd = 0; hd < 64; hd++) {
            float a[4], b[4];
            *(float4*)a = *(float4*)&Qts[hd * PAD + ty * 4];
            *(float4*)b = *(float4*)&Kts[hd * PAD + tx * 4];
            #pragma unroll
            for (int i = 0; i < 4; i++)
                #pragma unroll
                for (int j = 0; j < 4; j++)
                    s[i][j] += a[i] * b[j];
        }

        // scale + adjacency mask + online softmax
        #pragma unroll
        for (int i = 0; i < 4; i++) {
            int qr = q0 + ty * 4 + i;
            unsigned mw = mrow[(size_t)qr * 32 + kt * 2 + wsel];
            #pragma unroll
            for (int j = 0; j < 4; j++) {
                float sv = s[i][j] * 0.125f;     // 1/sqrt(64)
                if (!((mw >> (bit0 + j)) & 1u)) sv += NEGV;
                s[i][j] = sv;
            }
            float rm = fmaxf(fmaxf(s[i][0], s[i][1]), fmaxf(s[i][2], s[i][3]));
            #pragma unroll
            for (int o = 8; o > 0; o >>= 1)
                rm = fmaxf(rm, __shfl_xor_sync(0xffffffffu, rm, o, 16));
            float mnew = fmaxf(m_i[i], rm);
            float corr = __expf(m_i[i] - mnew);
            float rs = 0.f;
            #pragma unroll
            for (int j = 0; j < 4; j++) {
                float p = __expf(s[i][j] - mnew);
                s[i][j] = p;
                rs += p;
            }
            #pragma unroll
            for (int o = 8; o > 0; o >>= 1)
                rs += __shfl_xor_sync(0xffffffffu, rs, o, 16);
            l_i[i] = l_i[i] * corr + rs;
            m_i[i] = mnew;
            #pragma unroll
            for (int j = 0; j < 4; j++) acc[i][j] *= corr;
            // stash P row chunk
            float4 p4; p4.x = s[i][0]; p4.y = s[i][1]; p4.z = s[i][2]; p4.w = s[i][3];
            *(float4*)&Ps[(ty * 4 + i) * PAD + tx * 4] = p4;
        }
        __syncthreads();

        // acc += P @ V (contraction over kcol)
        #pragma unroll 8
        for (int kc = 0; kc < 64; kc++) {
            float a0 = Ps[(ty * 4 + 0) * PAD + kc];
            float a1 = Ps[(ty * 4 + 1) * PAD + kc];
            float a2 = Ps[(ty * 4 + 2) * PAD + kc];
            float a3 = Ps[(ty * 4 + 3) * PAD + kc];
            float b[4];
            *(float4*)b = *(float4*)&Vs[kc * PAD + tx * 4];
            #pragma unroll
            for (int j = 0; j < 4; j++) {
                acc[0][j] += a0 * b[j];
                acc[1][j] += a1 * b[j];
                acc[2][j] += a2 * b[j];
                acc[3][j] += a3 * b[j];
            }
        }
    }

    // epilogue: normalize, relu, write h[b][s][h*64+hd]
    #pragma unroll
    for (int i = 0; i < 4; i++) {
        float inv = 1.f / l_i[i];
        int qr = q0 + ty * 4 + i;
        float4 o;
        o.x = fmaxf(acc[i][0] * inv, 0.f);
        o.y = fmaxf(acc[i][1] * inv, 0.f);
        o.z = fmaxf(acc[i][2] * inv, 0.f);
        o.w = fmaxf(acc[i][3] * inv, 0.f);
        *(float4*)(out + ((size_t)bb * SS + qr) * DD + h * HD + tx * 4) = o;
    }
}

// ---------------------------------------------------------------------------
extern "C" void kernel_launch(void* const* d_in, const int* in_sizes, int n_in,
                              void* d_out, int out_size)
{
    const float* x   = (const float*)d_in[0];
    const float* adj = (const float*)d_in[1];
    const float* Wq  = (const float*)d_in[2];
    const float* bq  = (const float*)d_in[3];
    const float* Wk  = (const float*)d_in[4];
    const float* bk  = (const float*)d_in[5];
    const float* Wv  = (const float*)d_in[6];
    const float* bv  = (const float*)d_in[7];

    float* out     = (float*)d_out;
    float* out_adj = out + (size_t)BB * SS * DD;

    qkv_gemm<<<dim3(DD / BN, (BB * SS) / BM, 3), 256>>>(x, Wq, bq, Wk, bk, Wv, bv);
    mask_pack<<<(BB * SS * (SS / 32)) / 256, 256>>>(adj, out_adj);

    cudaFuncSetAttribute(attn, cudaFuncAttributeMaxDynamicSharedMemorySize,
                         4 * 64 * PAD * sizeof(float));
    attn<<<dim3(SS / 64, HH, BB), 256, 4 * 64 * PAD * sizeof(float)>>>(out);
}

// round 3
// speedup vs baseline: 1.3302x; 1.3302x over previous
#include <cuda_runtime.h>
#include <cuda_bf16.h>
#include <cstdint>

#define BB 4
#define SS 1024
#define DD 1024
#define HH 16
#define HD 64
#define NEGV -10000000.0f

// ---------------------------------------------------------------------------
// Scratch (allocation-free rule: __device__ globals)
// ---------------------------------------------------------------------------
__device__ float g_q[BB*HH*SS*HD];
__device__ float g_k[BB*HH*SS*HD];
__device__ float g_v[BB*HH*SS*HD];
__device__ unsigned g_mask[BB*SS*(SS/32)];
__device__ __nv_bfloat16 g_xhi[BB*SS*DD];
__device__ __nv_bfloat16 g_xlo[BB*SS*DD];
__device__ __nv_bfloat16 g_whi[3][DD*DD];   // transposed: [n][k]
__device__ __nv_bfloat16 g_wlo[3][DD*DD];

// ---------------------------------------------------------------------------
// mma.sync helper (bf16 -> fp32), baseline PTX (works on compute_103)
// ---------------------------------------------------------------------------
__device__ __forceinline__ void mma16816(
    float& d0, float& d1, float& d2, float& d3,
    uint32_t a0, uint32_t a1, uint32_t a2, uint32_t a3,
    uint32_t b0, uint32_t b1)
{
    asm volatile(
        "mma.sync.aligned.m16n8k16.row.col.f32.bf16.bf16.f32 "
        "{%0,%1,%2,%3}, {%4,%5,%6,%7}, {%8,%9}, {%0,%1,%2,%3};"
        : "+f"(d0), "+f"(d1), "+f"(d2), "+f"(d3)
        : "r"(a0), "r"(a1), "r"(a2), "r"(a3), "r"(b0), "r"(b1));
}

// ---------------------------------------------------------------------------
// Prep: split x into bf16 hi/lo
// ---------------------------------------------------------------------------
__global__ __launch_bounds__(256) void conv_x(const float* __restrict__ x)
{
    size_t i = ((size_t)blockIdx.x * 256 + threadIdx.x) * 4;
    float4 v = *(const float4*)(x + i);
    __nv_bfloat16 h0 = __float2bfloat16(v.x);
    __nv_bfloat16 h1 = __float2bfloat16(v.y);
    __nv_bfloat16 h2 = __float2bfloat16(v.z);
    __nv_bfloat16 h3 = __float2bfloat16(v.w);
    __nv_bfloat16 l0 = __float2bfloat16(v.x - __bfloat162float(h0));
    __nv_bfloat16 l1 = __float2bfloat16(v.y - __bfloat162float(h1));
    __nv_bfloat16 l2 = __float2bfloat16(v.z - __bfloat162float(h2));
    __nv_bfloat16 l3 = __float2bfloat16(v.w - __bfloat162float(h3));
    __nv_bfloat162 p;
    p.x = h0; p.y = h1; *(__nv_bfloat162*)(g_xhi + i)     = p;
    p.x = h2; p.y = h3; *(__nv_bfloat162*)(g_xhi + i + 2) = p;
    p.x = l0; p.y = l1; *(__nv_bfloat162*)(g_xlo + i)     = p;
    p.x = l2; p.y = l3; *(__nv_bfloat162*)(g_xlo + i + 2) = p;
}

// ---------------------------------------------------------------------------
// Prep: transpose W [K,N] -> Wt [N,K], split hi/lo
// ---------------------------------------------------------------------------
__global__ __launch_bounds__(256) void conv_w(
    const float* __restrict__ Wq, const float* __restrict__ Wk, const float* __restrict__ Wv)
{
    const int z = blockIdx.z;
    const float* W = z == 0 ? Wq : (z == 1 ? Wk : Wv);
    __shared__ float t[32][33];
    int tx = threadIdx.x, ty = threadIdx.y;
    int n0 = blockIdx.x * 32, k0 = blockIdx.y * 32;
    #pragma unroll
    for (int r = 0; r < 4; r++) {
        int k = k0 + ty + r * 8;
        t[ty + r * 8][tx] = W[(size_t)k * DD + n0 + tx];
    }
    __syncthreads();
    #pragma unroll
    for (int r = 0; r < 4; r++) {
        int nn = n0 + ty + r * 8;
        int kk = k0 + tx;
        float v = t[tx][ty + r * 8];
        __nv_bfloat16 hi = __float2bfloat16(v);
        __nv_bfloat16 lo = __float2bfloat16(v - __bfloat162float(hi));
        g_whi[z][(size_t)nn * DD + kk] = hi;
        g_wlo[z][(size_t)nn * DD + kk] = lo;
    }
}

// ---------------------------------------------------------------------------
// QKV GEMM via mma.sync: C[4096,1024] = X @ W (+bias), bf16-split 3 terms.
// CTA 128x128, 8 warps (2Mx4N), warp tile 64x32, K-chunk 32.
// SMEM rows padded to 40 bf16 (80B) to spread banks.
// ---------------------------------------------------------------------------
#define KP 40

__global__ __launch_bounds__(256) void qkv_gemm_mma(
    const float* __restrict__ bq, const float* __restrict__ bk, const float* __restrict__ bv)
{
    __shared__ __nv_bfloat16 Ah[128][KP], Al[128][KP], Bh[128][KP], Bl[128][KP];

    const int tid  = threadIdx.x;
    const int lane = tid & 31;
    const int wid  = tid >> 5;
    const int wm   = wid >> 2;          // 0..1  (64-row slab)
    const int wn   = wid & 3;           // 0..3  (32-col slab)
    const int z    = blockIdx.z;
    const int m0   = blockIdx.y * 128;
    const int n0   = blockIdx.x * 128;

    const __nv_bfloat16* __restrict__ gAh = g_xhi;
    const __nv_bfloat16* __restrict__ gAl = g_xlo;
    const __nv_bfloat16* __restrict__ gBh = g_whi[z];
    const __nv_bfloat16* __restrict__ gBl = g_wlo[z];
    const float* bias = z == 0 ? bq : (z == 1 ? bk : bv);
    float* out = z == 0 ? g_q : (z == 1 ? g_k : g_v);

    float acc[4][4][4];
    #pragma unroll
    for (int mt = 0; mt < 4; mt++)
        #pragma unroll
        for (int nt = 0; nt < 4; nt++)
            #pragma unroll
            for (int r = 0; r < 4; r++) acc[mt][nt][r] = 0.f;

    const int lrow = tid >> 1;          // 0..127 (two threads per row)
    const int lk8  = (tid & 1) * 16;    // 0 or 16: each thread does two 8-elem segs

    const int fr = lane >> 2;           // fragment row/col within tile
    const int fc = (lane & 3) * 2;

    for (int c = 0; c < 32; c++) {
        const int k0 = c * 32;
        // prefetch gmem into regs
        uint4 va0 = *(const uint4*)(gAh + (size_t)(m0 + lrow) * DD + k0 + lk8);
        uint4 va1 = *(const uint4*)(gAh + (size_t)(m0 + lrow) * DD + k0 + lk8 + 8);
        uint4 wa0 = *(const uint4*)(gAl + (size_t)(m0 + lrow) * DD + k0 + lk8);
        uint4 wa1 = *(const uint4*)(gAl + (size_t)(m0 + lrow) * DD + k0 + lk8 + 8);
        uint4 vb0 = *(const uint4*)(gBh + (size_t)(n0 + lrow) * DD + k0 + lk8);
        uint4 vb1 = *(const uint4*)(gBh + (size_t)(n0 + lrow) * DD + k0 + lk8 + 8);
        uint4 wb0 = *(const uint4*)(gBl + (size_t)(n0 + lrow) * DD + k0 + lk8);
        uint4 wb1 = *(const uint4*)(gBl + (size_t)(n0 + lrow) * DD + k0 + lk8 + 8);
        __syncthreads();
        *(uint4*)&Ah[lrow][lk8]     = va0;
        *(uint4*)&Ah[lrow][lk8 + 8] = va1;
        *(uint4*)&Al[lrow][lk8]     = wa0;
        *(uint4*)&Al[lrow][lk8 + 8] = wa1;
        *(uint4*)&Bh[lrow][lk8]     = vb0;
        *(uint4*)&Bh[lrow][lk8 + 8] = vb1;
        *(uint4*)&Bl[lrow][lk8]     = wb0;
        *(uint4*)&Bl[lrow][lk8 + 8] = wb1;
        __syncthreads();

        #pragma unroll
        for (int ks = 0; ks < 2; ks++) {
            const int kk = ks * 16;
            uint32_t ah[4][4], al[4][4], bh[4][2], bl[4][2];
            #pragma unroll
            for (int mt = 0; mt < 4; mt++) {
                const int rb = wm * 64 + mt * 16;
                ah[mt][0] = *(const uint32_t*)&Ah[rb + fr][kk + fc];
                ah[mt][1] = *(const uint32_t*)&Ah[rb + fr + 8][kk + fc];
                ah[mt][2] = *(const uint32_t*)&Ah[rb + fr][kk + fc + 8];
                ah[mt][3] = *(const uint32_t*)&Ah[rb + fr + 8][kk + fc + 8];
                al[mt][0] = *(const uint32_t*)&Al[rb + fr][kk + fc];
                al[mt][1] = *(const uint32_t*)&Al[rb + fr + 8][kk + fc];
                al[mt][2] = *(const uint32_t*)&Al[rb + fr][kk + fc + 8];
                al[mt][3] = *(const uint32_t*)&Al[rb + fr + 8][kk + fc + 8];
            }
            #pragma unroll
            for (int nt = 0; nt < 4; nt++) {
                const int nb = wn * 32 + nt * 8;
                bh[nt][0] = *(const uint32_t*)&Bh[nb + fr][kk + fc];
                bh[nt][1] = *(const uint32_t*)&Bh[nb + fr][kk + fc + 8];
                bl[nt][0] = *(const uint32_t*)&Bl[nb + fr][kk + fc];
                bl[nt][1] = *(const uint32_t*)&Bl[nb + fr][kk + fc + 8];
            }
            #pragma unroll
            for (int mt = 0; mt < 4; mt++)
                #pragma unroll
                for (int nt = 0; nt < 4; nt++) {
                    float* d = acc[mt][nt];
                    mma16816(d[0], d[1], d[2], d[3],
                             ah[mt][0], ah[mt][1], ah[mt][2], ah[mt][3],
                             bh[nt][0], bh[nt][1]);
                    mma16816(d[0], d[1], d[2], d[3],
                             ah[mt][0], ah[mt][1], ah[mt][2], ah[mt][3],
                             bl[nt][0], bl[nt][1]);
                    mma16816(d[0], d[1], d[2], d[3],
                             al[mt][0], al[mt][1], al[mt][2], al[mt][3],
                             bh[nt][0], bh[nt][1]);
                }
        }
    }

    // Epilogue: bias + scatter to [b,h,s,hd]
    #pragma unroll
    for (int nt = 0; nt < 4; nt++) {
        const int n = n0 + wn * 32 + nt * 8 + fc;
        const int h = n >> 6;
        const int hd = n & 63;
        const float bv0 = bias[n];
        const float bv1 = bias[n + 1];
        #pragma unroll
        for (int mt = 0; mt < 4; mt++) {
            #pragma unroll
            for (int half = 0; half < 2; half++) {
                const int m = m0 + wm * 64 + mt * 16 + fr + half * 8;
                const int bb = m >> 10;
                const int s = m & 1023;
                float2 o;
                o.x = acc[mt][nt][half * 2 + 0] + bv0;
                o.y = acc[mt][nt][half * 2 + 1] + bv1;
                *(float2*)(out + ((size_t)(bb * HH + h) * SS + s) * HD + hd) = o;
            }
        }
    }
}

// ---------------------------------------------------------------------------
// Pack adj into 1-bit mask and copy adj to second output region.
// ---------------------------------------------------------------------------
__global__ __launch_bounds__(256) void mask_pack(
    const float* __restrict__ adj, float* __restrict__ adj_out)
{
    int w = blockIdx.x * blockDim.x + threadIdx.x;
    const float4* a4 = (const float4*)adj;
    float4* o4 = (float4*)adj_out;
    unsigned bits = 0;
    #pragma unroll
    for (int i = 0; i < 8; i++) {
        float4 v = a4[(size_t)w * 8 + i];
        o4[(size_t)w * 8 + i] = v;
        bits |= (v.x >= 0.5f ? 1u : 0u) << (i * 4 + 0);
        bits |= (v.y >= 0.5f ? 1u : 0u) << (i * 4 + 1);
        bits |= (v.z >= 0.5f ? 1u : 0u) << (i * 4 + 2);
        bits |= (v.w >= 0.5f ? 1u : 0u) << (i * 4 + 3);
    }
    g_mask[w] = bits;
}

// ---------------------------------------------------------------------------
// Flash attention (fp32 SIMT): block = (q-tile 64, head, batch); 256 threads.
// ---------------------------------------------------------------------------
#define PAD 68

__global__ __launch_bounds__(256) void attn(float* __restrict__ out)
{
    extern __shared__ float smf[];
    float* Qts = smf;
    float* Kts = smf + 64 * PAD;
    float* Vs  = smf + 2 * 64 * PAD;
    float* Ps  = smf + 3 * 64 * PAD;

    const int tid = threadIdx.x;
    const int tx  = tid & 15;
    const int ty  = tid >> 4;
    const int q0  = blockIdx.x * 64;
    const int h   = blockIdx.y;
    const int bb  = blockIdx.z;

    const float* qb = g_q + ((size_t)(bb * HH + h) * SS) * HD;
    const float* kb = g_k + ((size_t)(bb * HH + h) * SS) * HD;
    const float* vb = g_v + ((size_t)(bb * HH + h) * SS) * HD;

    #pragma unroll
    for (int i = 0; i < 4; i++) {
        int f   = tid + i * 256;
        int row = f >> 4;
        int c4  = (f & 15) * 4;
        float4 v = *(const float4*)(qb + (size_t)(q0 + row) * HD + c4);
        Qts[(c4 + 0) * PAD + row] = v.x;
        Qts[(c4 + 1) * PAD + row] = v.y;
        Qts[(c4 + 2) * PAD + row] = v.z;
        Qts[(c4 + 3) * PAD + row] = v.w;
    }

    float m_i[4], l_i[4], acc[4][4];
    #pragma unroll
    for (int i = 0; i < 4; i++) {
        m_i[i] = -1e30f; l_i[i] = 0.f;
        #pragma unroll
        for (int j = 0; j < 4; j++) acc[i][j] = 0.f;
    }

    const unsigned* mrow = g_mask + (size_t)bb * SS * (SS / 32);
    const int wsel = tx >> 3;
    const int bit0 = (tx & 7) * 4;

    for (int kt = 0; kt < 16; kt++) {
        __syncthreads();
        #pragma unroll
        for (int i = 0; i < 4; i++) {
            int f   = tid + i * 256;
            int row = f >> 4;
            int c4  = (f & 15) * 4;
            float4 kv = *(const float4*)(kb + (size_t)(kt * 64 + row) * HD + c4);
            Kts[(c4 + 0) * PAD + row] = kv.x;
            Kts[(c4 + 1) * PAD + row] = kv.y;
            Kts[(c4 + 2) * PAD + row] = kv.z;
            Kts[(c4 + 3) * PAD + row] = kv.w;
            float4 vv = *(const float4*)(vb + (size_t)(kt * 64 + row) * HD + c4);
            *(float4*)&Vs[row * PAD + c4] = vv;
        }
        __syncthreads();

        float s[4][4];
        #pragma unroll
        for (int i = 0; i < 4; i++)
            #pragma unroll
            for (int j = 0; j < 4; j++) s[i][j] = 0.f;
        #pragma unroll 8
        for (int hd = 0; hd < 64; hd++) {
            float a[4], b[4];
            *(float4*)a = *(float4*)&Qts[hd * PAD + ty * 4];
            *(float4*)b = *(float4*)&Kts[hd * PAD + tx * 4];
            #pragma unroll
            for (int i = 0; i < 4; i++)
                #pragma unroll
                for (int j = 0; j < 4; j++)
                    s[i][j] += a[i] * b[j];
        }

        #pragma unroll
        for (int i = 0; i < 4; i++) {
            int qr = q0 + ty * 4 + i;
            unsigned mw = mrow[(size_t)qr * 32 + kt * 2 + wsel];
            #pragma unroll
            for (int j = 0; j < 4; j++) {
                float sv = s[i][j] * 0.125f;
                if (!((mw >> (bit0 + j)) & 1u)) sv += NEGV;
                s[i][j] = sv;
            }
            float rm = fmaxf(fmaxf(s[i][0], s[i][1]), fmaxf(s[i][2], s[i][3]));
            #pragma unroll
            for (int o = 8; o > 0; o >>= 1)
                rm = fmaxf(rm, __shfl_xor_sync(0xffffffffu, rm, o, 16));
            float mnew = fmaxf(m_i[i], rm);
            float corr = __expf(m_i[i] - mnew);
            float rs = 0.f;
            #pragma unroll
            for (int j = 0; j < 4; j++) {
                float p = __expf(s[i][j] - mnew);
                s[i][j] = p;
                rs += p;
            }
            #pragma unroll
            for (int o = 8; o > 0; o >>= 1)
                rs += __shfl_xor_sync(0xffffffffu, rs, o, 16);
            l_i[i] = l_i[i] * corr + rs;
            m_i[i] = mnew;
            #pragma unroll
            for (int j = 0; j < 4; j++) acc[i][j] *= corr;
            float4 p4; p4.x = s[i][0]; p4.y = s[i][1]; p4.z = s[i][2]; p4.w = s[i][3];
            *(float4*)&Ps[(ty * 4 + i) * PAD + tx * 4] = p4;
        }
        __syncthreads();

        #pragma unroll 8
        for (int kc = 0; kc < 64; kc++) {
            float a0 = Ps[(ty * 4 + 0) * PAD + kc];
            float a1 = Ps[(ty * 4 + 1) * PAD + kc];
            float a2 = Ps[(ty * 4 + 2) * PAD + kc];
            float a3 = Ps[(ty * 4 + 3) * PAD + kc];
            float b[4];
            *(float4*)b = *(float4*)&Vs[kc * PAD + tx * 4];
            #pragma unroll
            for (int j = 0; j < 4; j++) {
                acc[0][j] += a0 * b[j];
                acc[1][j] += a1 * b[j];
                acc[2][j] += a2 * b[j];
                acc[3][j] += a3 * b[j];
            }
        }
    }

    #pragma unroll
    for (int i = 0; i < 4; i++) {
        float inv = 1.f / l_i[i];
        int qr = q0 + ty * 4 + i;
        float4 o;
        o.x = fmaxf(acc[i][0] * inv, 0.f);
        o.y = fmaxf(acc[i][1] * inv, 0.f);
        o.z = fmaxf(acc[i][2] * inv, 0.f);
        o.w = fmaxf(acc[i][3] * inv, 0.f);
        *(float4*)(out + ((size_t)bb * SS + qr) * DD + h * HD + tx * 4) = o;
    }
}

// ---------------------------------------------------------------------------
extern "C" void kernel_launch(void* const* d_in, const int* in_sizes, int n_in,
                              void* d_out, int out_size)
{
    const float* x   = (const float*)d_in[0];
    const float* adj = (const float*)d_in[1];
    const float* Wq  = (const float*)d_in[2];
    const float* bq  = (const float*)d_in[3];
    const float* Wk  = (const float*)d_in[4];
    const float* bk  = (const float*)d_in[5];
    const float* Wv  = (const float*)d_in[6];
    const float* bv  = (const float*)d_in[7];

    float* out     = (float*)d_out;
    float* out_adj = out + (size_t)BB * SS * DD;

    conv_x<<<(BB * SS * DD) / (256 * 4), 256>>>(x);
    conv_w<<<dim3(DD / 32, DD / 32, 3), dim3(32, 8)>>>(Wq, Wk, Wv);
    mask_pack<<<(BB * SS * (SS / 32)) / 256, 256>>>(adj, out_adj);

    qkv_gemm_mma<<<dim3(DD / 128, (BB * SS) / 128, 3), 256>>>(bq, bk, bv);

    cudaFuncSetAttribute(attn, cudaFuncAttributeMaxDynamicSharedMemorySize,
                         4 * 64 * PAD * sizeof(float));
    attn<<<dim3(SS / 64, HH, BB), 256, 4 * 64 * PAD * sizeof(float)>>>(out);
}

// round 4
// speedup vs baseline: 2.0736x; 1.5589x over previous
#include <cuda_runtime.h>
#include <cuda_bf16.h>
#include <cstdint>

#define BB 4
#define SS 1024
#define DD 1024
#define HH 16
#define HD 64
#define NEGV -10000000.0f

// ---------------------------------------------------------------------------
// Scratch (__device__ globals; no allocation allowed)
// ---------------------------------------------------------------------------
__device__ float g_v[BB*HH*SS*HD];                 // V fp32 (pre-transpose)
__device__ unsigned g_mask[BB*SS*(SS/32)];
__device__ __nv_bfloat16 g_xhi[BB*SS*DD];
__device__ __nv_bfloat16 g_xlo[BB*SS*DD];
__device__ __nv_bfloat16 g_whi[3][DD*DD];          // transposed: [n][k]
__device__ __nv_bfloat16 g_wlo[3][DD*DD];
__device__ __nv_bfloat16 g_qhi[BB*HH*SS*HD];       // [b,h,s,hd]
__device__ __nv_bfloat16 g_qlo[BB*HH*SS*HD];
__device__ __nv_bfloat16 g_khi[BB*HH*SS*HD];       // [b,h,s,hd]
__device__ __nv_bfloat16 g_klo[BB*HH*SS*HD];
__device__ __nv_bfloat16 g_vthi[BB*HH*HD*SS];      // [b,h,hd,s]  (transposed)
__device__ __nv_bfloat16 g_vtlo[BB*HH*HD*SS];

// ---------------------------------------------------------------------------
// mma.sync helper (bf16 -> fp32), baseline PTX
// ---------------------------------------------------------------------------
__device__ __forceinline__ void mma16816(
    float& d0, float& d1, float& d2, float& d3,
    uint32_t a0, uint32_t a1, uint32_t a2, uint32_t a3,
    uint32_t b0, uint32_t b1)
{
    asm volatile(
        "mma.sync.aligned.m16n8k16.row.col.f32.bf16.bf16.f32 "
        "{%0,%1,%2,%3}, {%4,%5,%6,%7}, {%8,%9}, {%0,%1,%2,%3};"
        : "+f"(d0), "+f"(d1), "+f"(d2), "+f"(d3)
        : "r"(a0), "r"(a1), "r"(a2), "r"(a3), "r"(b0), "r"(b1));
}

__device__ __forceinline__ uint32_t smem_u32(const void* p) {
    uint32_t a;
    asm("{ .reg .u64 t; cvta.to.shared.u64 t, %1; cvt.u32.u64 %0, t; }"
        : "=r"(a) : "l"(p));
    return a;
}

__device__ __forceinline__ void cp16(uint32_t dst, const void* src) {
    asm volatile("cp.async.cg.shared.global [%0], [%1], 16;" :: "r"(dst), "l"(src));
}
#define CP_COMMIT() asm volatile("cp.async.commit_group;" ::: "memory")

// ---------------------------------------------------------------------------
// Prep: split x into bf16 hi/lo
// ---------------------------------------------------------------------------
__global__ __launch_bounds__(256) void conv_x(const float* __restrict__ x)
{
    size_t i = ((size_t)blockIdx.x * 256 + threadIdx.x) * 4;
    float4 v = *(const float4*)(x + i);
    __nv_bfloat16 h0 = __float2bfloat16(v.x);
    __nv_bfloat16 h1 = __float2bfloat16(v.y);
    __nv_bfloat16 h2 = __float2bfloat16(v.z);
    __nv_bfloat16 h3 = __float2bfloat16(v.w);
    __nv_bfloat16 l0 = __float2bfloat16(v.x - __bfloat162float(h0));
    __nv_bfloat16 l1 = __float2bfloat16(v.y - __bfloat162float(h1));
    __nv_bfloat16 l2 = __float2bfloat16(v.z - __bfloat162float(h2));
    __nv_bfloat16 l3 = __float2bfloat16(v.w - __bfloat162float(h3));
    __nv_bfloat162 p;
    p.x = h0; p.y = h1; *(__nv_bfloat162*)(g_xhi + i)     = p;
    p.x = h2; p.y = h3; *(__nv_bfloat162*)(g_xhi + i + 2) = p;
    p.x = l0; p.y = l1; *(__nv_bfloat162*)(g_xlo + i)     = p;
    p.x = l2; p.y = l3; *(__nv_bfloat162*)(g_xlo + i + 2) = p;
}

// ---------------------------------------------------------------------------
// Prep: transpose W [K,N] -> Wt [N,K], split hi/lo
// ---------------------------------------------------------------------------
__global__ __launch_bounds__(256) void conv_w(
    const float* __restrict__ Wq, const float* __restrict__ Wk, const float* __restrict__ Wv)
{
    const int z = blockIdx.z;
    const float* W = z == 0 ? Wq : (z == 1 ? Wk : Wv);
    __shared__ float t[32][33];
    int tx = threadIdx.x, ty = threadIdx.y;
    int n0 = blockIdx.x * 32, k0 = blockIdx.y * 32;
    #pragma unroll
    for (int r = 0; r < 4; r++) {
        int k = k0 + ty + r * 8;
        t[ty + r * 8][tx] = W[(size_t)k * DD + n0 + tx];
    }
    __syncthreads();
    #pragma unroll
    for (int r = 0; r < 4; r++) {
        int nn = n0 + ty + r * 8;
        int kk = k0 + tx;
        float v = t[tx][ty + r * 8];
        __nv_bfloat16 hi = __float2bfloat16(v);
        __nv_bfloat16 lo = __float2bfloat16(v - __bfloat162float(hi));
        g_whi[z][(size_t)nn * DD + kk] = hi;
        g_wlo[z][(size_t)nn * DD + kk] = lo;
    }
}

// ---------------------------------------------------------------------------
// QKV GEMM via mma.sync (as R3). Q/K epilogue writes bf16 hi/lo; V writes f32.
// ---------------------------------------------------------------------------
#define KP 40

__global__ __launch_bounds__(256) void qkv_gemm_mma(
    const float* __restrict__ bq, const float* __restrict__ bk, const float* __restrict__ bv)
{
    __shared__ __nv_bfloat16 Ah[128][KP], Al[128][KP], Bh[128][KP], Bl[128][KP];

    const int tid  = threadIdx.x;
    const int lane = tid & 31;
    const int wid  = tid >> 5;
    const int wm   = wid >> 2;
    const int wn   = wid & 3;
    const int z    = blockIdx.z;
    const int m0   = blockIdx.y * 128;
    const int n0   = blockIdx.x * 128;

    const __nv_bfloat16* __restrict__ gAh = g_xhi;
    const __nv_bfloat16* __restrict__ gAl = g_xlo;
    const __nv_bfloat16* __restrict__ gBh = g_whi[z];
    const __nv_bfloat16* __restrict__ gBl = g_wlo[z];
    const float* bias = z == 0 ? bq : (z == 1 ? bk : bv);

    float acc[4][4][4];
    #pragma unroll
    for (int mt = 0; mt < 4; mt++)
        #pragma unroll
        for (int nt = 0; nt < 4; nt++)
            #pragma unroll
            for (int r = 0; r < 4; r++) acc[mt][nt][r] = 0.f;

    const int lrow = tid >> 1;
    const int lk8  = (tid & 1) * 16;
    const int fr = lane >> 2;
    const int fc = (lane & 3) * 2;

    for (int c = 0; c < 32; c++) {
        const int k0 = c * 32;
        uint4 va0 = *(const uint4*)(gAh + (size_t)(m0 + lrow) * DD + k0 + lk8);
        uint4 va1 = *(const uint4*)(gAh + (size_t)(m0 + lrow) * DD + k0 + lk8 + 8);
        uint4 wa0 = *(const uint4*)(gAl + (size_t)(m0 + lrow) * DD + k0 + lk8);
        uint4 wa1 = *(const uint4*)(gAl + (size_t)(m0 + lrow) * DD + k0 + lk8 + 8);
        uint4 vb0 = *(const uint4*)(gBh + (size_t)(n0 + lrow) * DD + k0 + lk8);
        uint4 vb1 = *(const uint4*)(gBh + (size_t)(n0 + lrow) * DD + k0 + lk8 + 8);
        uint4 wb0 = *(const uint4*)(gBl + (size_t)(n0 + lrow) * DD + k0 + lk8);
        uint4 wb1 = *(const uint4*)(gBl + (size_t)(n0 + lrow) * DD + k0 + lk8 + 8);
        __syncthreads();
        *(uint4*)&Ah[lrow][lk8]     = va0;
        *(uint4*)&Ah[lrow][lk8 + 8] = va1;
        *(uint4*)&Al[lrow][lk8]     = wa0;
        *(uint4*)&Al[lrow][lk8 + 8] = wa1;
        *(uint4*)&Bh[lrow][lk8]     = vb0;
        *(uint4*)&Bh[lrow][lk8 + 8] = vb1;
        *(uint4*)&Bl[lrow][lk8]     = wb0;
        *(uint4*)&Bl[lrow][lk8 + 8] = wb1;
        __syncthreads();

        #pragma unroll
        for (int ks = 0; ks < 2; ks++) {
            const int kk = ks * 16;
            uint32_t ah[4][4], al[4][4], bh[4][2], bl[4][2];
            #pragma unroll
            for (int mt = 0; mt < 4; mt++) {
                const int rb = wm * 64 + mt * 16;
                ah[mt][0] = *(const uint32_t*)&Ah[rb + fr][kk + fc];
                ah[mt][1] = *(const uint32_t*)&Ah[rb + fr + 8][kk + fc];
                ah[mt][2] = *(const uint32_t*)&Ah[rb + fr][kk + fc + 8];
                ah[mt][3] = *(const uint32_t*)&Ah[rb + fr + 8][kk + fc + 8];
                al[mt][0] = *(const uint32_t*)&Al[rb + fr][kk + fc];
                al[mt][1] = *(const uint32_t*)&Al[rb + fr + 8][kk + fc];
                al[mt][2] = *(const uint32_t*)&Al[rb + fr][kk + fc + 8];
                al[mt][3] = *(const uint32_t*)&Al[rb + fr + 8][kk + fc + 8];
            }
            #pragma unroll
            for (int nt = 0; nt < 4; nt++) {
                const int nb = wn * 32 + nt * 8;
                bh[nt][0] = *(const uint32_t*)&Bh[nb + fr][kk + fc];
                bh[nt][1] = *(const uint32_t*)&Bh[nb + fr][kk + fc + 8];
                bl[nt][0] = *(const uint32_t*)&Bl[nb + fr][kk + fc];
                bl[nt][1] = *(const uint32_t*)&Bl[nb + fr][kk + fc + 8];
            }
            #pragma unroll
            for (int mt = 0; mt < 4; mt++)
                #pragma unroll
                for (int nt = 0; nt < 4; nt++) {
                    float* d = acc[mt][nt];
                    mma16816(d[0], d[1], d[2], d[3],
                             ah[mt][0], ah[mt][1], ah[mt][2], ah[mt][3],
                             bh[nt][0], bh[nt][1]);
                    mma16816(d[0], d[1], d[2], d[3],
                             ah[mt][0], ah[mt][1], ah[mt][2], ah[mt][3],
                             bl[nt][0], bl[nt][1]);
                    mma16816(d[0], d[1], d[2], d[3],
                             al[mt][0], al[mt][1], al[mt][2], al[mt][3],
                             bh[nt][0], bh[nt][1]);
                }
        }
    }

    __nv_bfloat16* ohi = z == 0 ? g_qhi : g_khi;
    __nv_bfloat16* olo = z == 0 ? g_qlo : g_klo;

    #pragma unroll
    for (int nt = 0; nt < 4; nt++) {
        const int n = n0 + wn * 32 + nt * 8 + fc;
        const int h = n >> 6;
        const int hd = n & 63;
        const float bv0 = bias[n];
        const float bv1 = bias[n + 1];
        #pragma unroll
        for (int mt = 0; mt < 4; mt++) {
            #pragma unroll
            for (int half = 0; half < 2; half++) {
                const int m = m0 + wm * 64 + mt * 16 + fr + half * 8;
                const int bb = m >> 10;
                const int s = m & 1023;
                float v0 = acc[mt][nt][half * 2 + 0] + bv0;
                float v1 = acc[mt][nt][half * 2 + 1] + bv1;
                size_t idx = ((size_t)(bb * HH + h) * SS + s) * HD + hd;
                if (z < 2) {
                    __nv_bfloat162 hv = __floats2bfloat162_rn(v0, v1);
                    __nv_bfloat162 lv = __floats2bfloat162_rn(
                        v0 - __bfloat162float(hv.x), v1 - __bfloat162float(hv.y));
                    *(__nv_bfloat162*)(ohi + idx) = hv;
                    *(__nv_bfloat162*)(olo + idx) = lv;
                } else {
                    float2 o; o.x = v0; o.y = v1;
                    *(float2*)(g_v + idx) = o;
                }
            }
        }
    }
}

// ---------------------------------------------------------------------------
// V: transpose [b,h,s,hd] f32 -> [b,h,hd,s] bf16 hi/lo
// ---------------------------------------------------------------------------
__global__ __launch_bounds__(256) void v_conv()
{
    __shared__ float t[32][33];
    const int bh = blockIdx.z;
    const int s0 = blockIdx.x * 32;
    const int hd0 = blockIdx.y * 32;
    const int tx = threadIdx.x, ty = threadIdx.y;
    #pragma unroll
    for (int r = 0; r < 4; r++) {
        int s = s0 + ty + r * 8;
        t[ty + r * 8][tx] = g_v[((size_t)bh * SS + s) * HD + hd0 + tx];
    }
    __syncthreads();
    #pragma unroll
    for (int r = 0; r < 4; r++) {
        int hd = hd0 + ty + r * 8;
        int s = s0 + tx;
        float v = t[tx][ty + r * 8];
        __nv_bfloat16 hi = __float2bfloat16(v);
        __nv_bfloat16 lo = __float2bfloat16(v - __bfloat162float(hi));
        g_vthi[((size_t)bh * HD + hd) * SS + s] = hi;
        g_vtlo[((size_t)bh * HD + hd) * SS + s] = lo;
    }
}

// ---------------------------------------------------------------------------
// Pack adj into 1-bit mask and copy adj to second output region.
// ---------------------------------------------------------------------------
__global__ __launch_bounds__(256) void mask_pack(
    const float* __restrict__ adj, float* __restrict__ adj_out)
{
    int w = blockIdx.x * blockDim.x + threadIdx.x;
    const float4* a4 = (const float4*)adj;
    float4* o4 = (float4*)adj_out;
    unsigned bits = 0;
    #pragma unroll
    for (int i = 0; i < 8; i++) {
        float4 v = a4[(size_t)w * 8 + i];
        o4[(size_t)w * 8 + i] = v;
        bits |= (v.x >= 0.5f ? 1u : 0u) << (i * 4 + 0);
        bits |= (v.y >= 0.5f ? 1u : 0u) << (i * 4 + 1);
        bits |= (v.z >= 0.5f ? 1u : 0u) << (i * 4 + 2);
        bits |= (v.w >= 0.5f ? 1u : 0u) << (i * 4 + 3);
    }
    g_mask[w] = bits;
}

// ---------------------------------------------------------------------------
// Flash attention via mma.sync, bf16-split 3-term for QK^T and PV.
// Block: q-tile 64 x head x batch; 128 threads (4 warps x 16 q-rows).
// K/V tiles double-buffered with cp.async. V is [hd][s] (pre-transposed).
// ---------------------------------------------------------------------------
#define AQP 72    // padded row length (elements) for 64-wide tiles
#define T_ELEM (64 * AQP)

__global__ __launch_bounds__(128) void attn_mma(float* __restrict__ out)
{
    extern __shared__ __nv_bfloat16 smp[];
    __nv_bfloat16* Qh = smp;                // [64][AQP]
    __nv_bfloat16* Ql = Qh + T_ELEM;
    __nv_bfloat16* KV = Ql + T_ELEM;        // 2 stages x {Kh,Kl,Vh,Vl}

    const int tid  = threadIdx.x;
    const int lane = tid & 31;
    const int warp = tid >> 5;
    const int g    = lane >> 2;
    const int t    = lane & 3;
    const int q0   = blockIdx.x * 64;
    const int h    = blockIdx.y;
    const int bb   = blockIdx.z;
    const int wq0  = warp * 16;

    const size_t bhs = ((size_t)(bb * HH + h)) * SS;
    const __nv_bfloat16* gqh = g_qhi + (bhs + q0) * HD;
    const __nv_bfloat16* gql = g_qlo + (bhs + q0) * HD;
    const __nv_bfloat16* gkh = g_khi + bhs * HD;
    const __nv_bfloat16* gkl = g_klo + bhs * HD;
    const __nv_bfloat16* gvh = g_vthi + ((size_t)(bb * HH + h)) * HD * SS;
    const __nv_bfloat16* gvl = g_vtlo + ((size_t)(bb * HH + h)) * HD * SS;

    const uint32_t sQh = smem_u32(Qh);
    const uint32_t sQl = smem_u32(Ql);
    const uint32_t sKV = smem_u32(KV);

    // ---- issue Q + tile 0 (group 0) ----
    {
        const int row = tid >> 3;           // 0..15 base; 4 chunks each of 16 rows
        const int seg = tid & 7;
        #pragma unroll
        for (int j = 0; j < 4; j++) {
            int r = row + j * 16;
            uint32_t doff = (uint32_t)(r * AQP + seg * 8) * 2;
            cp16(sQh + doff, gqh + (size_t)r * HD + seg * 8);
            cp16(sQl + doff, gql + (size_t)r * HD + seg * 8);
        }
        #pragma unroll
        for (int j = 0; j < 4; j++) {
            int r = row + j * 16;
            uint32_t doff = (uint32_t)(r * AQP + seg * 8) * 2;
            cp16(sKV + 0 * T_ELEM * 2 + doff, gkh + (size_t)r * HD + seg * 8);
            cp16(sKV + 1 * T_ELEM * 2 + doff, gkl + (size_t)r * HD + seg * 8);
            cp16(sKV + 2 * T_ELEM * 2 + doff, gvh + (size_t)r * SS + seg * 8);
            cp16(sKV + 3 * T_ELEM * 2 + doff, gvl + (size_t)r * SS + seg * 8);
        }
        CP_COMMIT();
    }

    float o_acc[8][4];
    #pragma unroll
    for (int nt = 0; nt < 8; nt++)
        #pragma unroll
        for (int e = 0; e < 4; e++) o_acc[nt][e] = 0.f;
    float m0v = -1e30f, m1v = -1e30f, l0v = 0.f, l1v = 0.f;

    const unsigned* mrow = g_mask + (size_t)bb * SS * (SS / 32);
    const int r0g = q0 + wq0 + g;
    const int r1g = r0g + 8;

    for (int kt = 0; kt < 16; kt++) {
        const int cur = kt & 1;
        // prefetch next tile
        if (kt + 1 < 16) {
            const int nxt = (kt + 1) & 1;
            const uint32_t base = sKV + (uint32_t)(nxt * 4 * T_ELEM) * 2;
            const int row = tid >> 3;
            const int seg = tid & 7;
            const size_t koff = (size_t)(kt + 1) * 64;
            #pragma unroll
            for (int j = 0; j < 4; j++) {
                int r = row + j * 16;
                uint32_t doff = (uint32_t)(r * AQP + seg * 8) * 2;
                cp16(base + 0 * T_ELEM * 2 + doff, gkh + (koff + r) * HD + seg * 8);
                cp16(base + 1 * T_ELEM * 2 + doff, gkl + (koff + r) * HD + seg * 8);
                cp16(base + 2 * T_ELEM * 2 + doff, gvh + (size_t)r * SS + koff + seg * 8);
                cp16(base + 3 * T_ELEM * 2 + doff, gvl + (size_t)r * SS + koff + seg * 8);
            }
            CP_COMMIT();
            asm volatile("cp.async.wait_group 1;" ::: "memory");
        } else {
            asm volatile("cp.async.wait_group 0;" ::: "memory");
        }
        __syncthreads();

        const __nv_bfloat16* Kh = KV + (cur * 4 + 0) * T_ELEM;
        const __nv_bfloat16* Kl = KV + (cur * 4 + 1) * T_ELEM;
        const __nv_bfloat16* Vh = KV + (cur * 4 + 2) * T_ELEM;
        const __nv_bfloat16* Vl = KV + (cur * 4 + 3) * T_ELEM;

        // ---- S = Q K^T (3-term split) ----
        float sf[8][4];
        #pragma unroll
        for (int nt = 0; nt < 8; nt++)
            #pragma unroll
            for (int e = 0; e < 4; e++) sf[nt][e] = 0.f;

        #pragma unroll
        for (int kk = 0; kk < 4; kk++) {
            const int kb = kk * 16;
            uint32_t qah[4], qal[4];
            qah[0] = *(const uint32_t*)&Qh[(wq0 + g) * AQP + kb + 2 * t];
            qah[1] = *(const uint32_t*)&Qh[(wq0 + g + 8) * AQP + kb + 2 * t];
            qah[2] = *(const uint32_t*)&Qh[(wq0 + g) * AQP + kb + 2 * t + 8];
            qah[3] = *(const uint32_t*)&Qh[(wq0 + g + 8) * AQP + kb + 2 * t + 8];
            qal[0] = *(const uint32_t*)&Ql[(wq0 + g) * AQP + kb + 2 * t];
            qal[1] = *(const uint32_t*)&Ql[(wq0 + g + 8) * AQP + kb + 2 * t];
            qal[2] = *(const uint32_t*)&Ql[(wq0 + g) * AQP + kb + 2 * t + 8];
            qal[3] = *(const uint32_t*)&Ql[(wq0 + g + 8) * AQP + kb + 2 * t + 8];
            #pragma unroll
            for (int nt = 0; nt < 8; nt++) {
                uint32_t bh0 = *(const uint32_t*)&Kh[(nt * 8 + g) * AQP + kb + 2 * t];
                uint32_t bh1 = *(const uint32_t*)&Kh[(nt * 8 + g) * AQP + kb + 2 * t + 8];
                uint32_t bl0 = *(const uint32_t*)&Kl[(nt * 8 + g) * AQP + kb + 2 * t];
                uint32_t bl1 = *(const uint32_t*)&Kl[(nt * 8 + g) * AQP + kb + 2 * t + 8];
                float* d = sf[nt];
                mma16816(d[0], d[1], d[2], d[3], qah[0], qah[1], qah[2], qah[3], bh0, bh1);
                mma16816(d[0], d[1], d[2], d[3], qah[0], qah[1], qah[2], qah[3], bl0, bl1);
                mma16816(d[0], d[1], d[2], d[3], qal[0], qal[1], qal[2], qal[3], bh0, bh1);
            }
        }

        // ---- mask + online softmax ----
        const unsigned w0 = mrow[(size_t)r0g * 32 + kt * 2];
        const unsigned w1 = mrow[(size_t)r0g * 32 + kt * 2 + 1];
        const unsigned w2 = mrow[(size_t)r1g * 32 + kt * 2];
        const unsigned w3 = mrow[(size_t)r1g * 32 + kt * 2 + 1];

        float mx0 = -1e30f, mx1 = -1e30f;
        #pragma unroll
        for (int nt = 0; nt < 8; nt++) {
            const unsigned wa = nt < 4 ? w0 : w1;
            const unsigned wb = nt < 4 ? w2 : w3;
            const int sh = (nt & 3) * 8 + 2 * t;
            float v0 = sf[nt][0] * 0.125f + (((wa >> sh) & 1u) ? 0.f : NEGV);
            float v1 = sf[nt][1] * 0.125f + (((wa >> (sh + 1)) & 1u) ? 0.f : NEGV);
            float v2 = sf[nt][2] * 0.125f + (((wb >> sh) & 1u) ? 0.f : NEGV);
            float v3 = sf[nt][3] * 0.125f + (((wb >> (sh + 1)) & 1u) ? 0.f : NEGV);
            sf[nt][0] = v0; sf[nt][1] = v1; sf[nt][2] = v2; sf[nt][3] = v3;
            mx0 = fmaxf(mx0, fmaxf(v0, v1));
            mx1 = fmaxf(mx1, fmaxf(v2, v3));
        }
        mx0 = fmaxf(mx0, __shfl_xor_sync(0xffffffffu, mx0, 1));
        mx0 = fmaxf(mx0, __shfl_xor_sync(0xffffffffu, mx0, 2));
        mx1 = fmaxf(mx1, __shfl_xor_sync(0xffffffffu, mx1, 1));
        mx1 = fmaxf(mx1, __shfl_xor_sync(0xffffffffu, mx1, 2));

        const float mn0 = fmaxf(m0v, mx0);
        const float mn1 = fmaxf(m1v, mx1);
        const float c0 = __expf(m0v - mn0);
        const float c1 = __expf(m1v - mn1);
        m0v = mn0; m1v = mn1;

        float sum0 = 0.f, sum1 = 0.f;
        uint32_t ph0[8], pl0[8], ph1[8], pl1[8];
        #pragma unroll
        for (int nt = 0; nt < 8; nt++) {
            float p00 = __expf(sf[nt][0] - mn0);
            float p01 = __expf(sf[nt][1] - mn0);
            float p10 = __expf(sf[nt][2] - mn1);
            float p11 = __expf(sf[nt][3] - mn1);
            sum0 += p00 + p01;
            sum1 += p10 + p11;
            __nv_bfloat162 hv0 = __floats2bfloat162_rn(p00, p01);
            __nv_bfloat162 lv0 = __floats2bfloat162_rn(
                p00 - __bfloat162float(hv0.x), p01 - __bfloat162float(hv0.y));
            __nv_bfloat162 hv1 = __floats2bfloat162_rn(p10, p11);
            __nv_bfloat162 lv1 = __floats2bfloat162_rn(
                p10 - __bfloat162float(hv1.x), p11 - __bfloat162float(hv1.y));
            ph0[nt] = *(uint32_t*)&hv0; pl0[nt] = *(uint32_t*)&lv0;
            ph1[nt] = *(uint32_t*)&hv1; pl1[nt] = *(uint32_t*)&lv1;
        }
        sum0 += __shfl_xor_sync(0xffffffffu, sum0, 1);
        sum0 += __shfl_xor_sync(0xffffffffu, sum0, 2);
        sum1 += __shfl_xor_sync(0xffffffffu, sum1, 1);
        sum1 += __shfl_xor_sync(0xffffffffu, sum1, 2);
        l0v = l0v * c0 + sum0;
        l1v = l1v * c1 + sum1;

        #pragma unroll
        for (int nt = 0; nt < 8; nt++) {
            o_acc[nt][0] *= c0; o_acc[nt][1] *= c0;
            o_acc[nt][2] *= c1; o_acc[nt][3] *= c1;
        }

        // ---- O += P V (3-term split) ----
        #pragma unroll
        for (int kc = 0; kc < 4; kc++) {
            const uint32_t ah0 = ph0[2 * kc],     ah1 = ph1[2 * kc];
            const uint32_t ah2 = ph0[2 * kc + 1], ah3 = ph1[2 * kc + 1];
            const uint32_t al0 = pl0[2 * kc],     al1 = pl1[2 * kc];
            const uint32_t al2 = pl0[2 * kc + 1], al3 = pl1[2 * kc + 1];
            #pragma unroll
            for (int nt = 0; nt < 8; nt++) {
                uint32_t bh0 = *(const uint32_t*)&Vh[(nt * 8 + g) * AQP + kc * 16 + 2 * t];
                uint32_t bh1 = *(const uint32_t*)&Vh[(nt * 8 + g) * AQP + kc * 16 + 2 * t + 8];
                uint32_t bl0 = *(const uint32_t*)&Vl[(nt * 8 + g) * AQP + kc * 16 + 2 * t];
                uint32_t bl1 = *(const uint32_t*)&Vl[(nt * 8 + g) * AQP + kc * 16 + 2 * t + 8];
                float* d = o_acc[nt];
                mma16816(d[0], d[1], d[2], d[3], ah0, ah1, ah2, ah3, bh0, bh1);
                mma16816(d[0], d[1], d[2], d[3], ah0, ah1, ah2, ah3, bl0, bl1);
                mma16816(d[0], d[1], d[2], d[3], al0, al1, al2, al3, bh0, bh1);
            }
        }
        __syncthreads();
    }

    // ---- epilogue: normalize, relu, write ----
    const float inv0 = 1.f / l0v;
    const float inv1 = 1.f / l1v;
    #pragma unroll
    for (int nt = 0; nt < 8; nt++) {
        const int col = h * 64 + nt * 8 + 2 * t;
        float2 oa, ob;
        oa.x = fmaxf(o_acc[nt][0] * inv0, 0.f);
        oa.y = fmaxf(o_acc[nt][1] * inv0, 0.f);
        ob.x = fmaxf(o_acc[nt][2] * inv1, 0.f);
        ob.y = fmaxf(o_acc[nt][3] * inv1, 0.f);
        *(float2*)(out + ((size_t)bb * SS + r0g) * DD + col) = oa;
        *(float2*)(out + ((size_t)bb * SS + r1g) * DD + col) = ob;
    }
}

// ---------------------------------------------------------------------------
extern "C" void kernel_launch(void* const* d_in, const int* in_sizes, int n_in,
                              void* d_out, int out_size)
{
    const float* x   = (const float*)d_in[0];
    const float* adj = (const float*)d_in[1];
    const float* Wq  = (const float*)d_in[2];
    const float* bq  = (const float*)d_in[3];
    const float* Wk  = (const float*)d_in[4];
    const float* bk  = (const float*)d_in[5];
    const float* Wv  = (const float*)d_in[6];
    const float* bv  = (const float*)d_in[7];

    float* out     = (float*)d_out;
    float* out_adj = out + (size_t)BB * SS * DD;

    conv_x<<<(BB * SS * DD) / (256 * 4), 256>>>(x);
    conv_w<<<dim3(DD / 32, DD / 32, 3), dim3(32, 8)>>>(Wq, Wk, Wv);
    mask_pack<<<(BB * SS * (SS / 32)) / 256, 256>>>(adj, out_adj);

    qkv_gemm_mma<<<dim3(DD / 128, (BB * SS) / 128, 3), 256>>>(bq, bk, bv);
    v_conv<<<dim3(SS / 32, HD / 32, BB * HH), dim3(32, 8)>>>();

    const int attn_smem = (2 * T_ELEM + 8 * T_ELEM) * (int)sizeof(__nv_bfloat16);
    cudaFuncSetAttribute(attn_mma, cudaFuncAttributeMaxDynamicSharedMemorySize, attn_smem);
    attn_mma<<<dim3(SS / 64, HH, BB), 128, attn_smem>>>(out);
}

// round 6
// speedup vs baseline: 2.6631x; 1.2843x over previous
#include <cuda_runtime.h>
#include <cuda_bf16.h>
#include <cstdint>

#define BB 4
#define SS 1024
#define DD 1024
#define HH 16
#define HD 64
#define NEGV -10000000.0f

// ---------------------------------------------------------------------------
// Scratch (__device__ globals; no allocation allowed)
// ---------------------------------------------------------------------------
__device__ float g_v[BB*HH*SS*HD];                 // V fp32 (pre-transpose)
__device__ unsigned g_mask[BB*SS*(SS/32)];
__device__ __nv_bfloat16 g_xhi[BB*SS*DD];
__device__ __nv_bfloat16 g_xlo[BB*SS*DD];
__device__ __nv_bfloat16 g_whi[3][DD*DD];          // transposed: [n][k]
__device__ __nv_bfloat16 g_wlo[3][DD*DD];
__device__ __nv_bfloat16 g_qhi[BB*HH*SS*HD];       // [b,h,s,hd]
__device__ __nv_bfloat16 g_qlo[BB*HH*SS*HD];
__device__ __nv_bfloat16 g_khi[BB*HH*SS*HD];       // [b,h,s,hd]
__device__ __nv_bfloat16 g_klo[BB*HH*SS*HD];
__device__ __nv_bfloat16 g_vthi[BB*HH*HD*SS];      // [b,h,hd,s]  (transposed)
__device__ __nv_bfloat16 g_vtlo[BB*HH*HD*SS];

// ---------------------------------------------------------------------------
// PTX helpers (baseline PTX only — works on plain sm_103 target)
// ---------------------------------------------------------------------------
__device__ __forceinline__ void mma16816(
    float& d0, float& d1, float& d2, float& d3,
    uint32_t a0, uint32_t a1, uint32_t a2, uint32_t a3,
    uint32_t b0, uint32_t b1)
{
    asm volatile(
        "mma.sync.aligned.m16n8k16.row.col.f32.bf16.bf16.f32 "
        "{%0,%1,%2,%3}, {%4,%5,%6,%7}, {%8,%9}, {%0,%1,%2,%3};"
        : "+f"(d0), "+f"(d1), "+f"(d2), "+f"(d3)
        : "r"(a0), "r"(a1), "r"(a2), "r"(a3), "r"(b0), "r"(b1));
}

__device__ __forceinline__ void ldm_x4(
    uint32_t& r0, uint32_t& r1, uint32_t& r2, uint32_t& r3, uint32_t addr)
{
    asm volatile("ldmatrix.sync.aligned.m8n8.x4.shared.b16 {%0,%1,%2,%3}, [%4];"
        : "=r"(r0), "=r"(r1), "=r"(r2), "=r"(r3) : "r"(addr));
}

__device__ __forceinline__ uint32_t smem_u32(const void* p) {
    uint32_t a;
    asm("{ .reg .u64 t; cvta.to.shared.u64 t, %1; cvt.u32.u64 %0, t; }"
        : "=r"(a) : "l"(p));
    return a;
}

__device__ __forceinline__ void cp16(uint32_t dst, const void* src) {
    asm volatile("cp.async.cg.shared.global [%0], [%1], 16;" :: "r"(dst), "l"(src));
}
#define CP_COMMIT() asm volatile("cp.async.commit_group;" ::: "memory")

// ---------------------------------------------------------------------------
// Prep: split x into bf16 hi/lo
// ---------------------------------------------------------------------------
__global__ __launch_bounds__(256) void conv_x(const float* __restrict__ x)
{
    size_t i = ((size_t)blockIdx.x * 256 + threadIdx.x) * 4;
    float4 v = *(const float4*)(x + i);
    __nv_bfloat16 h0 = __float2bfloat16(v.x);
    __nv_bfloat16 h1 = __float2bfloat16(v.y);
    __nv_bfloat16 h2 = __float2bfloat16(v.z);
    __nv_bfloat16 h3 = __float2bfloat16(v.w);
    __nv_bfloat16 l0 = __float2bfloat16(v.x - __bfloat162float(h0));
    __nv_bfloat16 l1 = __float2bfloat16(v.y - __bfloat162float(h1));
    __nv_bfloat16 l2 = __float2bfloat16(v.z - __bfloat162float(h2));
    __nv_bfloat16 l3 = __float2bfloat16(v.w - __bfloat162float(h3));
    __nv_bfloat162 p;
    p.x = h0; p.y = h1; *(__nv_bfloat162*)(g_xhi + i)     = p;
    p.x = h2; p.y = h3; *(__nv_bfloat162*)(g_xhi + i + 2) = p;
    p.x = l0; p.y = l1; *(__nv_bfloat162*)(g_xlo + i)     = p;
    p.x = l2; p.y = l3; *(__nv_bfloat162*)(g_xlo + i + 2) = p;
}

// ---------------------------------------------------------------------------
// Prep: transpose W [K,N] -> Wt [N,K], split hi/lo
// ---------------------------------------------------------------------------
__global__ __launch_bounds__(256) void conv_w(
    const float* __restrict__ Wq, const float* __restrict__ Wk, const float* __restrict__ Wv)
{
    const int z = blockIdx.z;
    const float* W = z == 0 ? Wq : (z == 1 ? Wk : Wv);
    __shared__ float t[32][33];
    int tx = threadIdx.x, ty = threadIdx.y;
    int n0 = blockIdx.x * 32, k0 = blockIdx.y * 32;
    #pragma unroll
    for (int r = 0; r < 4; r++) {
        int k = k0 + ty + r * 8;
        t[ty + r * 8][tx] = W[(size_t)k * DD + n0 + tx];
    }
    __syncthreads();
    #pragma unroll
    for (int r = 0; r < 4; r++) {
        int nn = n0 + ty + r * 8;
        int kk = k0 + tx;
        float v = t[tx][ty + r * 8];
        __nv_bfloat16 hi = __float2bfloat16(v);
        __nv_bfloat16 lo = __float2bfloat16(v - __bfloat162float(hi));
        g_whi[z][(size_t)nn * DD + kk] = hi;
        g_wlo[z][(size_t)nn * DD + kk] = lo;
    }
}

// ---------------------------------------------------------------------------
// QKV GEMM via mma.sync + cp.async double buffer + ldmatrix.
// CTA 128x128, 8 warps (2Mx4N), warp tile 64x32, K-chunk 32, 2 stages.
// Each SMEM array: 128 rows x 32 bf16, row stride KP2=40 elements.
// ---------------------------------------------------------------------------
#define KP2  40
#define GT   (128 * KP2)                 // elements per tile array
#define GSMB (2 * 4 * GT * 2)            // bytes total (2 stages x 4 arrays)

__global__ __launch_bounds__(256) void qkv_gemm_mma(
    const float* __restrict__ bq, const float* __restrict__ bk, const float* __restrict__ bv)
{
    extern __shared__ __nv_bfloat16 gsm[];

    const int tid  = threadIdx.x;
    const int lane = tid & 31;
    const int wid  = tid >> 5;
    const int wm   = wid >> 2;
    const int wn   = wid & 3;
    const int z    = blockIdx.z;
    const int m0   = blockIdx.y * 128;
    const int n0   = blockIdx.x * 128;

    const __nv_bfloat16* __restrict__ gAh = g_xhi;
    const __nv_bfloat16* __restrict__ gAl = g_xlo;
    const __nv_bfloat16* __restrict__ gBh = g_whi[z];
    const __nv_bfloat16* __restrict__ gBl = g_wlo[z];
    const float* bias = z == 0 ? bq : (z == 1 ? bk : bv);

    const uint32_t sb = smem_u32(gsm);

    float acc[4][4][4];
    #pragma unroll
    for (int mt = 0; mt < 4; mt++)
        #pragma unroll
        for (int nt = 0; nt < 4; nt++)
            #pragma unroll
            for (int r = 0; r < 4; r++) acc[mt][nt][r] = 0.f;

    const int fr = lane >> 2;
    const int fc = (lane & 3) * 2;

    // ---- chunk issue: 4 arrays x 128 rows x 32 bf16 (4 segs of 8/row) ----
    auto issue_chunk = [&](int c) {
        const uint32_t base = sb + (uint32_t)((c & 1) * 4 * GT) * 2;
        const int k0 = c * 32;
        #pragma unroll
        for (int i = 0; i < 2; i++) {
            const int idx = tid + i * 256;       // 0..511
            const int row = idx >> 2;            // 0..127
            const int seg = idx & 3;             // 0..3 (8 elems each)
            const uint32_t doff = (uint32_t)(row * KP2 + seg * 8) * 2;
            const size_t ao = (size_t)(m0 + row) * DD + k0 + seg * 8;
            const size_t bo = (size_t)(n0 + row) * DD + k0 + seg * 8;
            cp16(base + 0u * GT * 2 + doff, gAh + ao);
            cp16(base + 1u * GT * 2 + doff, gAl + ao);
            cp16(base + 2u * GT * 2 + doff, gBh + bo);
            cp16(base + 3u * GT * 2 + doff, gBl + bo);
        }
        CP_COMMIT();
    };

    issue_chunk(0);
    issue_chunk(1);

    for (int c = 0; c < 32; c++) {
        if (c == 31) asm volatile("cp.async.wait_group 0;" ::: "memory");
        else         asm volatile("cp.async.wait_group 1;" ::: "memory");
        __syncthreads();

        const uint32_t sbase = sb + (uint32_t)((c & 1) * 4 * GT) * 2;
        #pragma unroll
        for (int ks = 0; ks < 2; ks++) {
            const int kk = ks * 16;
            uint32_t ah[4][4], al[4][4], bh[4][2], bl[4][2];
            #pragma unroll
            for (int mt = 0; mt < 4; mt++) {
                const int rb = wm * 64 + mt * 16;
                const uint32_t aoff =
                    (uint32_t)((rb + (lane & 15)) * KP2 + kk + ((lane >> 4) << 3)) * 2;
                ldm_x4(ah[mt][0], ah[mt][1], ah[mt][2], ah[mt][3],
                       sbase + 0u * GT * 2 + aoff);
                ldm_x4(al[mt][0], al[mt][1], al[mt][2], al[mt][3],
                       sbase + 1u * GT * 2 + aoff);
            }
            #pragma unroll
            for (int np = 0; np < 2; np++) {
                const int nb = wn * 32 + np * 16;
                const uint32_t boff =
                    (uint32_t)((nb + (lane & 7) + ((lane >> 4) << 3)) * KP2 +
                               kk + (((lane >> 3) & 1) << 3)) * 2;
                ldm_x4(bh[np * 2][0], bh[np * 2][1], bh[np * 2 + 1][0], bh[np * 2 + 1][1],
                       sbase + 2u * GT * 2 + boff);
                ldm_x4(bl[np * 2][0], bl[np * 2][1], bl[np * 2 + 1][0], bl[np * 2 + 1][1],
                       sbase + 3u * GT * 2 + boff);
            }
            #pragma unroll
            for (int mt = 0; mt < 4; mt++)
                #pragma unroll
                for (int nt = 0; nt < 4; nt++) {
                    float* d = acc[mt][nt];
                    mma16816(d[0], d[1], d[2], d[3],
                             ah[mt][0], ah[mt][1], ah[mt][2], ah[mt][3],
                             bh[nt][0], bh[nt][1]);
                    mma16816(d[0], d[1], d[2], d[3],
                             ah[mt][0], ah[mt][1], ah[mt][2], ah[mt][3],
                             bl[nt][0], bl[nt][1]);
                    mma16816(d[0], d[1], d[2], d[3],
                             al[mt][0], al[mt][1], al[mt][2], al[mt][3],
                             bh[nt][0], bh[nt][1]);
                }
        }

        if (c + 2 < 32) {
            __syncthreads();          // all reads of this buffer done
            issue_chunk(c + 2);       // overwrite it
        }
    }

    __nv_bfloat16* ohi = z == 0 ? g_qhi : g_khi;
    __nv_bfloat16* olo = z == 0 ? g_qlo : g_klo;

    #pragma unroll
    for (int nt = 0; nt < 4; nt++) {
        const int n = n0 + wn * 32 + nt * 8 + fc;
        const int h = n >> 6;
        const int hd = n & 63;
        const float bv0 = bias[n];
        const float bv1 = bias[n + 1];
        #pragma unroll
        for (int mt = 0; mt < 4; mt++) {
            #pragma unroll
            for (int half = 0; half < 2; half++) {
                const int m = m0 + wm * 64 + mt * 16 + fr + half * 8;
                const int bb = m >> 10;
                const int s = m & 1023;
                float v0 = acc[mt][nt][half * 2 + 0] + bv0;
                float v1 = acc[mt][nt][half * 2 + 1] + bv1;
                size_t idx = ((size_t)(bb * HH + h) * SS + s) * HD + hd;
                if (z < 2) {
                    __nv_bfloat162 hv = __floats2bfloat162_rn(v0, v1);
                    __nv_bfloat162 lv = __floats2bfloat162_rn(
                        v0 - __bfloat162float(hv.x), v1 - __bfloat162float(hv.y));
                    *(__nv_bfloat162*)(ohi + idx) = hv;
                    *(__nv_bfloat162*)(olo + idx) = lv;
                } else {
                    float2 o; o.x = v0; o.y = v1;
                    *(float2*)(g_v + idx) = o;
                }
            }
        }
    }
}

// ---------------------------------------------------------------------------
// V: transpose [b,h,s,hd] f32 -> [b,h,hd,s] bf16 hi/lo
// ---------------------------------------------------------------------------
__global__ __launch_bounds__(256) void v_conv()
{
    __shared__ float t[32][33];
    const int bh = blockIdx.z;
    const int s0 = blockIdx.x * 32;
    const int hd0 = blockIdx.y * 32;
    const int tx = threadIdx.x, ty = threadIdx.y;
    #pragma unroll
    for (int r = 0; r < 4; r++) {
        int s = s0 + ty + r * 8;
        t[ty + r * 8][tx] = g_v[((size_t)bh * SS + s) * HD + hd0 + tx];
    }
    __syncthreads();
    #pragma unroll
    for (int r = 0; r < 4; r++) {
        int hd = hd0 + ty + r * 8;
        int s = s0 + tx;
        float v = t[tx][ty + r * 8];
        __nv_bfloat16 hi = __float2bfloat16(v);
        __nv_bfloat16 lo = __float2bfloat16(v - __bfloat162float(hi));
        g_vthi[((size_t)bh * HD + hd) * SS + s] = hi;
        g_vtlo[((size_t)bh * HD + hd) * SS + s] = lo;
    }
}

// ---------------------------------------------------------------------------
// Pack adj into 1-bit mask and copy adj to second output region.
// ---------------------------------------------------------------------------
__global__ __launch_bounds__(256) void mask_pack(
    const float* __restrict__ adj, float* __restrict__ adj_out)
{
    int w = blockIdx.x * blockDim.x + threadIdx.x;
    const float4* a4 = (const float4*)adj;
    float4* o4 = (float4*)adj_out;
    unsigned bits = 0;
    #pragma unroll
    for (int i = 0; i < 8; i++) {
        float4 v = a4[(size_t)w * 8 + i];
        o4[(size_t)w * 8 + i] = v;
        bits |= (v.x >= 0.5f ? 1u : 0u) << (i * 4 + 0);
        bits |= (v.y >= 0.5f ? 1u : 0u) << (i * 4 + 1);
        bits |= (v.z >= 0.5f ? 1u : 0u) << (i * 4 + 2);
        bits |= (v.w >= 0.5f ? 1u : 0u) << (i * 4 + 3);
    }
    g_mask[w] = bits;
}

// ---------------------------------------------------------------------------
// Flash attention via mma.sync (as R4): q-tile 64, 128 threads, cp.async DB.
// ---------------------------------------------------------------------------
#define AQP 72
#define T_ELEM (64 * AQP)

__global__ __launch_bounds__(128) void attn_mma(float* __restrict__ out)
{
    extern __shared__ __nv_bfloat16 smp[];
    __nv_bfloat16* Qh = smp;
    __nv_bfloat16* Ql = Qh + T_ELEM;
    __nv_bfloat16* KV = Ql + T_ELEM;

    const int tid  = threadIdx.x;
    const int lane = tid & 31;
    const int warp = tid >> 5;
    const int g    = lane >> 2;
    const int t    = lane & 3;
    const int q0   = blockIdx.x * 64;
    const int h    = blockIdx.y;
    const int bb   = blockIdx.z;
    const int wq0  = warp * 16;

    const size_t bhs = ((size_t)(bb * HH + h)) * SS;
    const __nv_bfloat16* gqh = g_qhi + (bhs + q0) * HD;
    const __nv_bfloat16* gql = g_qlo + (bhs + q0) * HD;
    const __nv_bfloat16* gkh = g_khi + bhs * HD;
    const __nv_bfloat16* gkl = g_klo + bhs * HD;
    const __nv_bfloat16* gvh = g_vthi + ((size_t)(bb * HH + h)) * HD * SS;
    const __nv_bfloat16* gvl = g_vtlo + ((size_t)(bb * HH + h)) * HD * SS;

    const uint32_t sQh = smem_u32(Qh);
    const uint32_t sQl = smem_u32(Ql);
    const uint32_t sKV = smem_u32(KV);

    {
        const int row = tid >> 3;
        const int seg = tid & 7;
        #pragma unroll
        for (int j = 0; j < 4; j++) {
            int r = row + j * 16;
            uint32_t doff = (uint32_t)(r * AQP + seg * 8) * 2;
            cp16(sQh + doff, gqh + (size_t)r * HD + seg * 8);
            cp16(sQl + doff, gql + (size_t)r * HD + seg * 8);
        }
        #pragma unroll
        for (int j = 0; j < 4; j++) {
            int r = row + j * 16;
            uint32_t doff = (uint32_t)(r * AQP + seg * 8) * 2;
            cp16(sKV + 0 * T_ELEM * 2 + doff, gkh + (size_t)r * HD + seg * 8);
            cp16(sKV + 1 * T_ELEM * 2 + doff, gkl + (size_t)r * HD + seg * 8);
            cp16(sKV + 2 * T_ELEM * 2 + doff, gvh + (size_t)r * SS + seg * 8);
            cp16(sKV + 3 * T_ELEM * 2 + doff, gvl + (size_t)r * SS + seg * 8);
        }
        CP_COMMIT();
    }

    float o_acc[8][4];
    #pragma unroll
    for (int nt = 0; nt < 8; nt++)
        #pragma unroll
        for (int e = 0; e < 4; e++) o_acc[nt][e] = 0.f;
    float m0v = -1e30f, m1v = -1e30f, l0v = 0.f, l1v = 0.f;

    const unsigned* mrow = g_mask + (size_t)bb * SS * (SS / 32);
    const int r0g = q0 + wq0 + g;
    const int r1g = r0g + 8;

    for (int kt = 0; kt < 16; kt++) {
        const int cur = kt & 1;
        if (kt + 1 < 16) {
            const int nxt = (kt + 1) & 1;
            const uint32_t base = sKV + (uint32_t)(nxt * 4 * T_ELEM) * 2;
            const int row = tid >> 3;
            const int seg = tid & 7;
            const size_t koff = (size_t)(kt + 1) * 64;
            #pragma unroll
            for (int j = 0; j < 4; j++) {
                int r = row + j * 16;
                uint32_t doff = (uint32_t)(r * AQP + seg * 8) * 2;
                cp16(base + 0 * T_ELEM * 2 + doff, gkh + (koff + r) * HD + seg * 8);
                cp16(base + 1 * T_ELEM * 2 + doff, gkl + (koff + r) * HD + seg * 8);
                cp16(base + 2 * T_ELEM * 2 + doff, gvh + (size_t)r * SS + koff + seg * 8);
                cp16(base + 3 * T_ELEM * 2 + doff, gvl + (size_t)r * SS + koff + seg * 8);
            }
            CP_COMMIT();
            asm volatile("cp.async.wait_group 1;" ::: "memory");
        } else {
            asm volatile("cp.async.wait_group 0;" ::: "memory");
        }
        __syncthreads();

        const __nv_bfloat16* Kh = KV + (cur * 4 + 0) * T_ELEM;
        const __nv_bfloat16* Kl = KV + (cur * 4 + 1) * T_ELEM;
        const __nv_bfloat16* Vh = KV + (cur * 4 + 2) * T_ELEM;
        const __nv_bfloat16* Vl = KV + (cur * 4 + 3) * T_ELEM;

        float sf[8][4];
        #pragma unroll
        for (int nt = 0; nt < 8; nt++)
            #pragma unroll
            for (int e = 0; e < 4; e++) sf[nt][e] = 0.f;

        #pragma unroll
        for (int kk = 0; kk < 4; kk++) {
            const int kb = kk * 16;
            uint32_t qah[4], qal[4];
            qah[0] = *(const uint32_t*)&Qh[(wq0 + g) * AQP + kb + 2 * t];
            qah[1] = *(const uint32_t*)&Qh[(wq0 + g + 8) * AQP + kb + 2 * t];
            qah[2] = *(const uint32_t*)&Qh[(wq0 + g) * AQP + kb + 2 * t + 8];
            qah[3] = *(const uint32_t*)&Qh[(wq0 + g + 8) * AQP + kb + 2 * t + 8];
            qal[0] = *(const uint32_t*)&Ql[(wq0 + g) * AQP + kb + 2 * t];
            qal[1] = *(const uint32_t*)&Ql[(wq0 + g + 8) * AQP + kb + 2 * t];
            qal[2] = *(const uint32_t*)&Ql[(wq0 + g) * AQP + kb + 2 * t + 8];
            qal[3] = *(const uint32_t*)&Ql[(wq0 + g + 8) * AQP + kb + 2 * t + 8];
            #pragma unroll
            for (int nt = 0; nt < 8; nt++) {
                uint32_t bh0 = *(const uint32_t*)&Kh[(nt * 8 + g) * AQP + kb + 2 * t];
                uint32_t bh1 = *(const uint32_t*)&Kh[(nt * 8 + g) * AQP + kb + 2 * t + 8];
                uint32_t bl0 = *(const uint32_t*)&Kl[(nt * 8 + g) * AQP + kb + 2 * t];
                uint32_t bl1 = *(const uint32_t*)&Kl[(nt * 8 + g) * AQP + kb + 2 * t + 8];
                float* d = sf[nt];
                mma16816(d[0], d[1], d[2], d[3], qah[0], qah[1], qah[2], qah[3], bh0, bh1);
                mma16816(d[0], d[1], d[2], d[3], qah[0], qah[1], qah[2], qah[3], bl0, bl1);
                mma16816(d[0], d[1], d[2], d[3], qal[0], qal[1], qal[2], qal[3], bh0, bh1);
            }
        }

        const unsigned w0 = mrow[(size_t)r0g * 32 + kt * 2];
        const unsigned w1 = mrow[(size_t)r0g * 32 + kt * 2 + 1];
        const unsigned w2 = mrow[(size_t)r1g * 32 + kt * 2];
        const unsigned w3 = mrow[(size_t)r1g * 32 + kt * 2 + 1];

        float mx0 = -1e30f, mx1 = -1e30f;
        #pragma unroll
        for (int nt = 0; nt < 8; nt++) {
            const unsigned wa = nt < 4 ? w0 : w1;
            const unsigned wb = nt < 4 ? w2 : w3;
            const int sh = (nt & 3) * 8 + 2 * t;
            float v0 = sf[nt][0] * 0.125f + (((wa >> sh) & 1u) ? 0.f : NEGV);
            float v1 = sf[nt][1] * 0.125f + (((wa >> (sh + 1)) & 1u) ? 0.f : NEGV);
            float v2 = sf[nt][2] * 0.125f + (((wb >> sh) & 1u) ? 0.f : NEGV);
            float v3 = sf[nt][3] * 0.125f + (((wb >> (sh + 1)) & 1u) ? 0.f : NEGV);
            sf[nt][0] = v0; sf[nt][1] = v1; sf[nt][2] = v2; sf[nt][3] = v3;
            mx0 = fmaxf(mx0, fmaxf(v0, v1));
            mx1 = fmaxf(mx1, fmaxf(v2, v3));
        }
        mx0 = fmaxf(mx0, __shfl_xor_sync(0xffffffffu, mx0, 1));
        mx0 = fmaxf(mx0, __shfl_xor_sync(0xffffffffu, mx0, 2));
        mx1 = fmaxf(mx1, __shfl_xor_sync(0xffffffffu, mx1, 1));
        mx1 = fmaxf(mx1, __shfl_xor_sync(0xffffffffu, mx1, 2));

        const float mn0 = fmaxf(m0v, mx0);
        const float mn1 = fmaxf(m1v, mx1);
        const float c0 = __expf(m0v - mn0);
        const float c1 = __expf(m1v - mn1);
        m0v = mn0; m1v = mn1;

        float sum0 = 0.f, sum1 = 0.f;
        uint32_t ph0[8], pl0[8], ph1[8], pl1[8];
        #pragma unroll
        for (int nt = 0; nt < 8; nt++) {
            float p00 = __expf(sf[nt][0] - mn0);
            float p01 = __expf(sf[nt][1] - mn0);
            float p10 = __expf(sf[nt][2] - mn1);
            float p11 = __expf(sf[nt][3] - mn1);
            sum0 += p00 + p01;
            sum1 += p10 + p11;
            __nv_bfloat162 hv0 = __floats2bfloat162_rn(p00, p01);
            __nv_bfloat162 lv0 = __floats2bfloat162_rn(
                p00 - __bfloat162float(hv0.x), p01 - __bfloat162float(hv0.y));
            __nv_bfloat162 hv1 = __floats2bfloat162_rn(p10, p11);
            __nv_bfloat162 lv1 = __floats2bfloat162_rn(
                p10 - __bfloat162float(hv1.x), p11 - __bfloat162float(hv1.y));
            ph0[nt] = *(uint32_t*)&hv0; pl0[nt] = *(uint32_t*)&lv0;
            ph1[nt] = *(uint32_t*)&hv1; pl1[nt] = *(uint32_t*)&lv1;
        }
        sum0 += __shfl_xor_sync(0xffffffffu, sum0, 1);
        sum0 += __shfl_xor_sync(0xffffffffu, sum0, 2);
        sum1 += __shfl_xor_sync(0xffffffffu, sum1, 1);
        sum1 += __shfl_xor_sync(0xffffffffu, sum1, 2);
        l0v = l0v * c0 + sum0;
        l1v = l1v * c1 + sum1;

        #pragma unroll
        for (int nt = 0; nt < 8; nt++) {
            o_acc[nt][0] *= c0; o_acc[nt][1] *= c0;
            o_acc[nt][2] *= c1; o_acc[nt][3] *= c1;
        }

        #pragma unroll
        for (int kc = 0; kc < 4; kc++) {
            const uint32_t ah0 = ph0[2 * kc],     ah1 = ph1[2 * kc];
            const uint32_t ah2 = ph0[2 * kc + 1], ah3 = ph1[2 * kc + 1];
            const uint32_t al0 = pl0[2 * kc],     al1 = pl1[2 * kc];
            const uint32_t al2 = pl0[2 * kc + 1], al3 = pl1[2 * kc + 1];
            #pragma unroll
            for (int nt = 0; nt < 8; nt++) {
                uint32_t bh0 = *(const uint32_t*)&Vh[(nt * 8 + g) * AQP + kc * 16 + 2 * t];
                uint32_t bh1 = *(const uint32_t*)&Vh[(nt * 8 + g) * AQP + kc * 16 + 2 * t + 8];
                uint32_t bl0 = *(const uint32_t*)&Vl[(nt * 8 + g) * AQP + kc * 16 + 2 * t];
                uint32_t bl1 = *(const uint32_t*)&Vl[(nt * 8 + g) * AQP + kc * 16 + 2 * t + 8];
                float* d = o_acc[nt];
                mma16816(d[0], d[1], d[2], d[3], ah0, ah1, ah2, ah3, bh0, bh1);
                mma16816(d[0], d[1], d[2], d[3], ah0, ah1, ah2, ah3, bl0, bl1);
                mma16816(d[0], d[1], d[2], d[3], al0, al1, al2, al3, bh0, bh1);
            }
        }
        __syncthreads();
    }

    const float inv0 = 1.f / l0v;
    const float inv1 = 1.f / l1v;
    #pragma unroll
    for (int nt = 0; nt < 8; nt++) {
        const int col = h * 64 + nt * 8 + 2 * t;
        float2 oa, ob;
        oa.x = fmaxf(o_acc[nt][0] * inv0, 0.f);
        oa.y = fmaxf(o_acc[nt][1] * inv0, 0.f);
        ob.x = fmaxf(o_acc[nt][2] * inv1, 0.f);
        ob.y = fmaxf(o_acc[nt][3] * inv1, 0.f);
        *(float2*)(out + ((size_t)bb * SS + r0g) * DD + col) = oa;
        *(float2*)(out + ((size_t)bb * SS + r1g) * DD + col) = ob;
    }
}

// ---------------------------------------------------------------------------
extern "C" void kernel_launch(void* const* d_in, const int* in_sizes, int n_in,
                              void* d_out, int out_size)
{
    const float* x   = (const float*)d_in[0];
    const float* adj = (const float*)d_in[1];
    const float* Wq  = (const float*)d_in[2];
    const float* bq  = (const float*)d_in[3];
    const float* Wk  = (const float*)d_in[4];
    const float* bk  = (const float*)d_in[5];
    const float* Wv  = (const float*)d_in[6];
    const float* bv  = (const float*)d_in[7];

    float* out     = (float*)d_out;
    float* out_adj = out + (size_t)BB * SS * DD;

    conv_x<<<(BB * SS * DD) / (256 * 4), 256>>>(x);
    conv_w<<<dim3(DD / 32, DD / 32, 3), dim3(32, 8)>>>(Wq, Wk, Wv);
    mask_pack<<<(BB * SS * (SS / 32)) / 256, 256>>>(adj, out_adj);

    cudaFuncSetAttribute(qkv_gemm_mma, cudaFuncAttributeMaxDynamicSharedMemorySize, GSMB);
    qkv_gemm_mma<<<dim3(DD / 128, (BB * SS) / 128, 3), 256, GSMB>>>(bq, bk, bv);
    v_conv<<<dim3(SS / 32, HD / 32, BB * HH), dim3(32, 8)>>>();

    const int attn_smem = (2 * T_ELEM + 8 * T_ELEM) * (int)sizeof(__nv_bfloat16);
    cudaFuncSetAttribute(attn_mma, cudaFuncAttributeMaxDynamicSharedMemorySize, attn_smem);
    attn_mma<<<dim3(SS / 64, HH, BB), 128, attn_smem>>>(out);
}

// round 7
// speedup vs baseline: 2.7124x; 1.0185x over previous
#include <cuda_runtime.h>
#include <cuda_bf16.h>
#include <cstdint>

#define BB 4
#define SS 1024
#define DD 1024
#define HH 16
#define HD 64
#define NEGV -10000000.0f

// ---------------------------------------------------------------------------
// Scratch (__device__ globals; no allocation allowed)
// ---------------------------------------------------------------------------
__device__ float g_v[BB*HH*SS*HD];                 // V fp32 (pre-transpose)
__device__ unsigned g_mask[BB*SS*(SS/32)];
__device__ __nv_bfloat16 g_xhi[BB*SS*DD];
__device__ __nv_bfloat16 g_xlo[BB*SS*DD];
__device__ __nv_bfloat16 g_whi[3][DD*DD];          // transposed: [n][k]
__device__ __nv_bfloat16 g_wlo[3][DD*DD];
__device__ __nv_bfloat16 g_qhi[BB*HH*SS*HD];       // [b,h,s,hd]
__device__ __nv_bfloat16 g_qlo[BB*HH*SS*HD];
__device__ __nv_bfloat16 g_khi[BB*HH*SS*HD];       // [b,h,s,hd]
__device__ __nv_bfloat16 g_klo[BB*HH*SS*HD];
__device__ __nv_bfloat16 g_vthi[BB*HH*HD*SS];      // [b,h,hd,s]  (transposed)
__device__ __nv_bfloat16 g_vtlo[BB*HH*HD*SS];

// ---------------------------------------------------------------------------
// PTX helpers (baseline PTX only — works on plain sm_103 target)
// ---------------------------------------------------------------------------
__device__ __forceinline__ void mma16816(
    float& d0, float& d1, float& d2, float& d3,
    uint32_t a0, uint32_t a1, uint32_t a2, uint32_t a3,
    uint32_t b0, uint32_t b1)
{
    asm volatile(
        "mma.sync.aligned.m16n8k16.row.col.f32.bf16.bf16.f32 "
        "{%0,%1,%2,%3}, {%4,%5,%6,%7}, {%8,%9}, {%0,%1,%2,%3};"
        : "+f"(d0), "+f"(d1), "+f"(d2), "+f"(d3)
        : "r"(a0), "r"(a1), "r"(a2), "r"(a3), "r"(b0), "r"(b1));
}

__device__ __forceinline__ void ldm_x4(
    uint32_t& r0, uint32_t& r1, uint32_t& r2, uint32_t& r3, uint32_t addr)
{
    asm volatile("ldmatrix.sync.aligned.m8n8.x4.shared.b16 {%0,%1,%2,%3}, [%4];"
        : "=r"(r0), "=r"(r1), "=r"(r2), "=r"(r3) : "r"(addr));
}

__device__ __forceinline__ uint32_t smem_u32(const void* p) {
    uint32_t a;
    asm("{ .reg .u64 t; cvta.to.shared.u64 t, %1; cvt.u32.u64 %0, t; }"
        : "=r"(a) : "l"(p));
    return a;
}

__device__ __forceinline__ void cp16(uint32_t dst, const void* src) {
    asm volatile("cp.async.cg.shared.global [%0], [%1], 16;" :: "r"(dst), "l"(src));
}
#define CP_COMMIT() asm volatile("cp.async.commit_group;" ::: "memory")

// ---------------------------------------------------------------------------
// Prep: split x into bf16 hi/lo
// ---------------------------------------------------------------------------
__global__ __launch_bounds__(256) void conv_x(const float* __restrict__ x)
{
    size_t i = ((size_t)blockIdx.x * 256 + threadIdx.x) * 4;
    float4 v = *(const float4*)(x + i);
    __nv_bfloat16 h0 = __float2bfloat16(v.x);
    __nv_bfloat16 h1 = __float2bfloat16(v.y);
    __nv_bfloat16 h2 = __float2bfloat16(v.z);
    __nv_bfloat16 h3 = __float2bfloat16(v.w);
    __nv_bfloat16 l0 = __float2bfloat16(v.x - __bfloat162float(h0));
    __nv_bfloat16 l1 = __float2bfloat16(v.y - __bfloat162float(h1));
    __nv_bfloat16 l2 = __float2bfloat16(v.z - __bfloat162float(h2));
    __nv_bfloat16 l3 = __float2bfloat16(v.w - __bfloat162float(h3));
    __nv_bfloat162 p;
    p.x = h0; p.y = h1; *(__nv_bfloat162*)(g_xhi + i)     = p;
    p.x = h2; p.y = h3; *(__nv_bfloat162*)(g_xhi + i + 2) = p;
    p.x = l0; p.y = l1; *(__nv_bfloat162*)(g_xlo + i)     = p;
    p.x = l2; p.y = l3; *(__nv_bfloat162*)(g_xlo + i + 2) = p;
}

// ---------------------------------------------------------------------------
// Prep: transpose W [K,N] -> Wt [N,K], split hi/lo
// ---------------------------------------------------------------------------
__global__ __launch_bounds__(256) void conv_w(
    const float* __restrict__ Wq, const float* __restrict__ Wk, const float* __restrict__ Wv)
{
    const int z = blockIdx.z;
    const float* W = z == 0 ? Wq : (z == 1 ? Wk : Wv);
    __shared__ float t[32][33];
    int tx = threadIdx.x, ty = threadIdx.y;
    int n0 = blockIdx.x * 32, k0 = blockIdx.y * 32;
    #pragma unroll
    for (int r = 0; r < 4; r++) {
        int k = k0 + ty + r * 8;
        t[ty + r * 8][tx] = W[(size_t)k * DD + n0 + tx];
    }
    __syncthreads();
    #pragma unroll
    for (int r = 0; r < 4; r++) {
        int nn = n0 + ty + r * 8;
        int kk = k0 + tx;
        float v = t[tx][ty + r * 8];
        __nv_bfloat16 hi = __float2bfloat16(v);
        __nv_bfloat16 lo = __float2bfloat16(v - __bfloat162float(hi));
        g_whi[z][(size_t)nn * DD + kk] = hi;
        g_wlo[z][(size_t)nn * DD + kk] = lo;
    }
}

// ---------------------------------------------------------------------------
// QKV GEMM via mma.sync + 4-stage cp.async pipeline (single barrier/chunk).
// CTA 128x128, 8 warps (2Mx4N), warp tile 64x32, K-chunk 32.
// Each SMEM array: 128 rows x 32 bf16, row stride KP2=40 elements.
// ---------------------------------------------------------------------------
#define KP2  40
#define GT   (128 * KP2)                 // elements per tile array
#define NSTG 4
#define GSMB (NSTG * 4 * GT * 2)         // bytes total (4 stages x 4 arrays)

__global__ __launch_bounds__(256) void qkv_gemm_mma(
    const float* __restrict__ bq, const float* __restrict__ bk, const float* __restrict__ bv)
{
    extern __shared__ __nv_bfloat16 gsm[];

    const int tid  = threadIdx.x;
    const int lane = tid & 31;
    const int wid  = tid >> 5;
    const int wm   = wid >> 2;
    const int wn   = wid & 3;
    const int z    = blockIdx.z;
    const int m0   = blockIdx.y * 128;
    const int n0   = blockIdx.x * 128;

    const __nv_bfloat16* __restrict__ gAh = g_xhi;
    const __nv_bfloat16* __restrict__ gAl = g_xlo;
    const __nv_bfloat16* __restrict__ gBh = g_whi[z];
    const __nv_bfloat16* __restrict__ gBl = g_wlo[z];
    const float* bias = z == 0 ? bq : (z == 1 ? bk : bv);

    const uint32_t sb = smem_u32(gsm);

    float acc[4][4][4];
    #pragma unroll
    for (int mt = 0; mt < 4; mt++)
        #pragma unroll
        for (int nt = 0; nt < 4; nt++)
            #pragma unroll
            for (int r = 0; r < 4; r++) acc[mt][nt][r] = 0.f;

    const int fr = lane >> 2;
    const int fc = (lane & 3) * 2;

    // ---- chunk issue: 4 arrays x 128 rows x 32 bf16 (4 segs of 8/row) ----
    auto issue_chunk = [&](int c) {
        const uint32_t base = sb + (uint32_t)((c & (NSTG - 1)) * 4 * GT) * 2;
        const int k0 = c * 32;
        #pragma unroll
        for (int i = 0; i < 2; i++) {
            const int idx = tid + i * 256;       // 0..511
            const int row = idx >> 2;            // 0..127
            const int seg = idx & 3;             // 0..3 (8 elems each)
            const uint32_t doff = (uint32_t)(row * KP2 + seg * 8) * 2;
            const size_t ao = (size_t)(m0 + row) * DD + k0 + seg * 8;
            const size_t bo = (size_t)(n0 + row) * DD + k0 + seg * 8;
            cp16(base + 0u * GT * 2 + doff, gAh + ao);
            cp16(base + 1u * GT * 2 + doff, gAl + ao);
            cp16(base + 2u * GT * 2 + doff, gBh + bo);
            cp16(base + 3u * GT * 2 + doff, gBl + bo);
        }
        CP_COMMIT();
    };

    issue_chunk(0);
    issue_chunk(1);
    issue_chunk(2);

    for (int c = 0; c < 32; c++) {
        // group c must be complete before compute(c)
        if (c < 30)       asm volatile("cp.async.wait_group 2;" ::: "memory");
        else if (c == 30) asm volatile("cp.async.wait_group 1;" ::: "memory");
        else              asm volatile("cp.async.wait_group 0;" ::: "memory");
        __syncthreads();

        const uint32_t sbase = sb + (uint32_t)((c & (NSTG - 1)) * 4 * GT) * 2;
        #pragma unroll
        for (int ks = 0; ks < 2; ks++) {
            const int kk = ks * 16;
            uint32_t ah[4][4], al[4][4], bh[4][2], bl[4][2];
            #pragma unroll
            for (int mt = 0; mt < 4; mt++) {
                const int rb = wm * 64 + mt * 16;
                const uint32_t aoff =
                    (uint32_t)((rb + (lane & 15)) * KP2 + kk + ((lane >> 4) << 3)) * 2;
                ldm_x4(ah[mt][0], ah[mt][1], ah[mt][2], ah[mt][3],
                       sbase + 0u * GT * 2 + aoff);
                ldm_x4(al[mt][0], al[mt][1], al[mt][2], al[mt][3],
                       sbase + 1u * GT * 2 + aoff);
            }
            #pragma unroll
            for (int np = 0; np < 2; np++) {
                const int nb = wn * 32 + np * 16;
                const uint32_t boff =
                    (uint32_t)((nb + (lane & 7) + ((lane >> 4) << 3)) * KP2 +
                               kk + (((lane >> 3) & 1) << 3)) * 2;
                ldm_x4(bh[np * 2][0], bh[np * 2][1], bh[np * 2 + 1][0], bh[np * 2 + 1][1],
                       sbase + 2u * GT * 2 + boff);
                ldm_x4(bl[np * 2][0], bl[np * 2][1], bl[np * 2 + 1][0], bl[np * 2 + 1][1],
                       sbase + 3u * GT * 2 + boff);
            }
            #pragma unroll
            for (int mt = 0; mt < 4; mt++)
                #pragma unroll
                for (int nt = 0; nt < 4; nt++) {
                    float* d = acc[mt][nt];
                    mma16816(d[0], d[1], d[2], d[3],
                             ah[mt][0], ah[mt][1], ah[mt][2], ah[mt][3],
                             bh[nt][0], bh[nt][1]);
                    mma16816(d[0], d[1], d[2], d[3],
                             ah[mt][0], ah[mt][1], ah[mt][2], ah[mt][3],
                             bl[nt][0], bl[nt][1]);
                    mma16816(d[0], d[1], d[2], d[3],
                             al[mt][0], al[mt][1], al[mt][2], al[mt][3],
                             bh[nt][0], bh[nt][1]);
                }
        }

        // Safe without a second barrier: buffer (c+3)%4 == (c-1)%4, whose
        // readers (compute c-1) finished before this iteration's barrier.
        if (c + 3 < 32) issue_chunk(c + 3);
    }

    __nv_bfloat16* ohi = z == 0 ? g_qhi : g_khi;
    __nv_bfloat16* olo = z == 0 ? g_qlo : g_klo;

    #pragma unroll
    for (int nt = 0; nt < 4; nt++) {
        const int n = n0 + wn * 32 + nt * 8 + fc;
        const int h = n >> 6;
        const int hd = n & 63;
        const float bv0 = bias[n];
        const float bv1 = bias[n + 1];
        #pragma unroll
        for (int mt = 0; mt < 4; mt++) {
            #pragma unroll
            for (int half = 0; half < 2; half++) {
                const int m = m0 + wm * 64 + mt * 16 + fr + half * 8;
                const int bb = m >> 10;
                const int s = m & 1023;
                float v0 = acc[mt][nt][half * 2 + 0] + bv0;
                float v1 = acc[mt][nt][half * 2 + 1] + bv1;
                size_t idx = ((size_t)(bb * HH + h) * SS + s) * HD + hd;
                if (z < 2) {
                    __nv_bfloat162 hv = __floats2bfloat162_rn(v0, v1);
                    __nv_bfloat162 lv = __floats2bfloat162_rn(
                        v0 - __bfloat162float(hv.x), v1 - __bfloat162float(hv.y));
                    *(__nv_bfloat162*)(ohi + idx) = hv;
                    *(__nv_bfloat162*)(olo + idx) = lv;
                } else {
                    float2 o; o.x = v0; o.y = v1;
                    *(float2*)(g_v + idx) = o;
                }
            }
        }
    }
}

// ---------------------------------------------------------------------------
// V: transpose [b,h,s,hd] f32 -> [b,h,hd,s] bf16 hi/lo
// ---------------------------------------------------------------------------
__global__ __launch_bounds__(256) void v_conv()
{
    __shared__ float t[32][33];
    const int bh = blockIdx.z;
    const int s0 = blockIdx.x * 32;
    const int hd0 = blockIdx.y * 32;
    const int tx = threadIdx.x, ty = threadIdx.y;
    #pragma unroll
    for (int r = 0; r < 4; r++) {
        int s = s0 + ty + r * 8;
        t[ty + r * 8][tx] = g_v[((size_t)bh * SS + s) * HD + hd0 + tx];
    }
    __syncthreads();
    #pragma unroll
    for (int r = 0; r < 4; r++) {
        int hd = hd0 + ty + r * 8;
        int s = s0 + tx;
        float v = t[tx][ty + r * 8];
        __nv_bfloat16 hi = __float2bfloat16(v);
        __nv_bfloat16 lo = __float2bfloat16(v - __bfloat162float(hi));
        g_vthi[((size_t)bh * HD + hd) * SS + s] = hi;
        g_vtlo[((size_t)bh * HD + hd) * SS + s] = lo;
    }
}

// ---------------------------------------------------------------------------
// Pack adj into 1-bit mask and copy adj to second output region.
// ---------------------------------------------------------------------------
__global__ __launch_bounds__(256) void mask_pack(
    const float* __restrict__ adj, float* __restrict__ adj_out)
{
    int w = blockIdx.x * blockDim.x + threadIdx.x;
    const float4* a4 = (const float4*)adj;
    float4* o4 = (float4*)adj_out;
    unsigned bits = 0;
    #pragma unroll
    for (int i = 0; i < 8; i++) {
        float4 v = a4[(size_t)w * 8 + i];
        o4[(size_t)w * 8 + i] = v;
        bits |= (v.x >= 0.5f ? 1u : 0u) << (i * 4 + 0);
        bits |= (v.y >= 0.5f ? 1u : 0u) << (i * 4 + 1);
        bits |= (v.z >= 0.5f ? 1u : 0u) << (i * 4 + 2);
        bits |= (v.w >= 0.5f ? 1u : 0u) << (i * 4 + 3);
    }
    g_mask[w] = bits;
}

// ---------------------------------------------------------------------------
// Flash attention via mma.sync: q-tile 64, 128 threads, cp.async DB.
// ---------------------------------------------------------------------------
#define AQP 72
#define T_ELEM (64 * AQP)

__global__ __launch_bounds__(128) void attn_mma(float* __restrict__ out)
{
    extern __shared__ __nv_bfloat16 smp[];
    __nv_bfloat16* Qh = smp;
    __nv_bfloat16* Ql = Qh + T_ELEM;
    __nv_bfloat16* KV = Ql + T_ELEM;

    const int tid  = threadIdx.x;
    const int lane = tid & 31;
    const int warp = tid >> 5;
    const int g    = lane >> 2;
    const int t    = lane & 3;
    const int q0   = blockIdx.x * 64;
    const int h    = blockIdx.y;
    const int bb   = blockIdx.z;
    const int wq0  = warp * 16;

    const size_t bhs = ((size_t)(bb * HH + h)) * SS;
    const __nv_bfloat16* gqh = g_qhi + (bhs + q0) * HD;
    const __nv_bfloat16* gql = g_qlo + (bhs + q0) * HD;
    const __nv_bfloat16* gkh = g_khi + bhs * HD;
    const __nv_bfloat16* gkl = g_klo + bhs * HD;
    const __nv_bfloat16* gvh = g_vthi + ((size_t)(bb * HH + h)) * HD * SS;
    const __nv_bfloat16* gvl = g_vtlo + ((size_t)(bb * HH + h)) * HD * SS;

    const uint32_t sQh = smem_u32(Qh);
    const uint32_t sQl = smem_u32(Ql);
    const uint32_t sKV = smem_u32(KV);

    {
        const int row = tid >> 3;
        const int seg = tid & 7;
        #pragma unroll
        for (int j = 0; j < 4; j++) {
            int r = row + j * 16;
            uint32_t doff = (uint32_t)(r * AQP + seg * 8) * 2;
            cp16(sQh + doff, gqh + (size_t)r * HD + seg * 8);
            cp16(sQl + doff, gql + (size_t)r * HD + seg * 8);
        }
        #pragma unroll
        for (int j = 0; j < 4; j++) {
            int r = row + j * 16;
            uint32_t doff = (uint32_t)(r * AQP + seg * 8) * 2;
            cp16(sKV + 0 * T_ELEM * 2 + doff, gkh + (size_t)r * HD + seg * 8);
            cp16(sKV + 1 * T_ELEM * 2 + doff, gkl + (size_t)r * HD + seg * 8);
            cp16(sKV + 2 * T_ELEM * 2 + doff, gvh + (size_t)r * SS + seg * 8);
            cp16(sKV + 3 * T_ELEM * 2 + doff, gvl + (size_t)r * SS + seg * 8);
        }
        CP_COMMIT();
    }

    float o_acc[8][4];
    #pragma unroll
    for (int nt = 0; nt < 8; nt++)
        #pragma unroll
        for (int e = 0; e < 4; e++) o_acc[nt][e] = 0.f;
    float m0v = -1e30f, m1v = -1e30f, l0v = 0.f, l1v = 0.f;

    const unsigned* mrow = g_mask + (size_t)bb * SS * (SS / 32);
    const int r0g = q0 + wq0 + g;
    const int r1g = r0g + 8;

    for (int kt = 0; kt < 16; kt++) {
        const int cur = kt & 1;
        if (kt + 1 < 16) {
            const int nxt = (kt + 1) & 1;
            const uint32_t base = sKV + (uint32_t)(nxt * 4 * T_ELEM) * 2;
            const int row = tid >> 3;
            const int seg = tid & 7;
            const size_t koff = (size_t)(kt + 1) * 64;
            #pragma unroll
            for (int j = 0; j < 4; j++) {
                int r = row + j * 16;
                uint32_t doff = (uint32_t)(r * AQP + seg * 8) * 2;
                cp16(base + 0 * T_ELEM * 2 + doff, gkh + (koff + r) * HD + seg * 8);
                cp16(base + 1 * T_ELEM * 2 + doff, gkl + (koff + r) * HD + seg * 8);
                cp16(base + 2 * T_ELEM * 2 + doff, gvh + (size_t)r * SS + koff + seg * 8);
                cp16(base + 3 * T_ELEM * 2 + doff, gvl + (size_t)r * SS + koff + seg * 8);
            }
            CP_COMMIT();
            asm volatile("cp.async.wait_group 1;" ::: "memory");
        } else {
            asm volatile("cp.async.wait_group 0;" ::: "memory");
        }
        __syncthreads();

        const __nv_bfloat16* Kh = KV + (cur * 4 + 0) * T_ELEM;
        const __nv_bfloat16* Kl = KV + (cur * 4 + 1) * T_ELEM;
        const __nv_bfloat16* Vh = KV + (cur * 4 + 2) * T_ELEM;
        const __nv_bfloat16* Vl = KV + (cur * 4 + 3) * T_ELEM;

        float sf[8][4];
        #pragma unroll
        for (int nt = 0; nt < 8; nt++)
            #pragma unroll
            for (int e = 0; e < 4; e++) sf[nt][e] = 0.f;

        #pragma unroll
        for (int kk = 0; kk < 4; kk++) {
            const int kb = kk * 16;
            uint32_t qah[4], qal[4];
            qah[0] = *(const uint32_t*)&Qh[(wq0 + g) * AQP + kb + 2 * t];
            qah[1] = *(const uint32_t*)&Qh[(wq0 + g + 8) * AQP + kb + 2 * t];
            qah[2] = *(const uint32_t*)&Qh[(wq0 + g) * AQP + kb + 2 * t + 8];
            qah[3] = *(const uint32_t*)&Qh[(wq0 + g + 8) * AQP + kb + 2 * t + 8];
            qal[0] = *(const uint32_t*)&Ql[(wq0 + g) * AQP + kb + 2 * t];
            qal[1] = *(const uint32_t*)&Ql[(wq0 + g + 8) * AQP + kb + 2 * t];
            qal[2] = *(const uint32_t*)&Ql[(wq0 + g) * AQP + kb + 2 * t + 8];
            qal[3] = *(const uint32_t*)&Ql[(wq0 + g + 8) * AQP + kb + 2 * t + 8];
            #pragma unroll
            for (int nt = 0; nt < 8; nt++) {
                uint32_t bh0 = *(const uint32_t*)&Kh[(nt * 8 + g) * AQP + kb + 2 * t];
                uint32_t bh1 = *(const uint32_t*)&Kh[(nt * 8 + g) * AQP + kb + 2 * t + 8];
                uint32_t bl0 = *(const uint32_t*)&Kl[(nt * 8 + g) * AQP + kb + 2 * t];
                uint32_t bl1 = *(const uint32_t*)&Kl[(nt * 8 + g) * AQP + kb + 2 * t + 8];
                float* d = sf[nt];
                mma16816(d[0], d[1], d[2], d[3], qah[0], qah[1], qah[2], qah[3], bh0, bh1);
                mma16816(d[0], d[1], d[2], d[3], qah[0], qah[1], qah[2], qah[3], bl0, bl1);
                mma16816(d[0], d[1], d[2], d[3], qal[0], qal[1], qal[2], qal[3], bh0, bh1);
            }
        }

        const unsigned w0 = mrow[(size_t)r0g * 32 + kt * 2];
        const unsigned w1 = mrow[(size_t)r0g * 32 + kt * 2 + 1];
        const unsigned w2 = mrow[(size_t)r1g * 32 + kt * 2];
        const unsigned w3 = mrow[(size_t)r1g * 32 + kt * 2 + 1];

        float mx0 = -1e30f, mx1 = -1e30f;
        #pragma unroll
        for (int nt = 0; nt < 8; nt++) {
            const unsigned wa = nt < 4 ? w0 : w1;
            const unsigned wb = nt < 4 ? w2 : w3;
            const int sh = (nt & 3) * 8 + 2 * t;
            float v0 = sf[nt][0] * 0.125f + (((wa >> sh) & 1u) ? 0.f : NEGV);
            float v1 = sf[nt][1] * 0.125f + (((wa >> (sh + 1)) & 1u) ? 0.f : NEGV);
            float v2 = sf[nt][2] * 0.125f + (((wb >> sh) & 1u) ? 0.f : NEGV);
            float v3 = sf[nt][3] * 0.125f + (((wb >> (sh + 1)) & 1u) ? 0.f : NEGV);
            sf[nt][0] = v0; sf[nt][1] = v1; sf[nt][2] = v2; sf[nt][3] = v3;
            mx0 = fmaxf(mx0, fmaxf(v0, v1));
            mx1 = fmaxf(mx1, fmaxf(v2, v3));
        }
        mx0 = fmaxf(mx0, __shfl_xor_sync(0xffffffffu, mx0, 1));
        mx0 = fmaxf(mx0, __shfl_xor_sync(0xffffffffu, mx0, 2));
        mx1 = fmaxf(mx1, __shfl_xor_sync(0xffffffffu, mx1, 1));
        mx1 = fmaxf(mx1, __shfl_xor_sync(0xffffffffu, mx1, 2));

        const float mn0 = fmaxf(m0v, mx0);
        const float mn1 = fmaxf(m1v, mx1);
        const float c0 = __expf(m0v - mn0);
        const float c1 = __expf(m1v - mn1);
        m0v = mn0; m1v = mn1;

        float sum0 = 0.f, sum1 = 0.f;
        uint32_t ph0[8], pl0[8], ph1[8], pl1[8];
        #pragma unroll
        for (int nt = 0; nt < 8; nt++) {
            float p00 = __expf(sf[nt][0] - mn0);
            float p01 = __expf(sf[nt][1] - mn0);
            float p10 = __expf(sf[nt][2] - mn1);
            float p11 = __expf(sf[nt][3] - mn1);
            sum0 += p00 + p01;
            sum1 += p10 + p11;
            __nv_bfloat162 hv0 = __floats2bfloat162_rn(p00, p01);
            __nv_bfloat162 lv0 = __floats2bfloat162_rn(
                p00 - __bfloat162float(hv0.x), p01 - __bfloat162float(hv0.y));
            __nv_bfloat162 hv1 = __floats2bfloat162_rn(p10, p11);
            __nv_bfloat162 lv1 = __floats2bfloat162_rn(
                p10 - __bfloat162float(hv1.x), p11 - __bfloat162float(hv1.y));
            ph0[nt] = *(uint32_t*)&hv0; pl0[nt] = *(uint32_t*)&lv0;
            ph1[nt] = *(uint32_t*)&hv1; pl1[nt] = *(uint32_t*)&lv1;
        }
        sum0 += __shfl_xor_sync(0xffffffffu, sum0, 1);
        sum0 += __shfl_xor_sync(0xffffffffu, sum0, 2);
        sum1 += __shfl_xor_sync(0xffffffffu, sum1, 1);
        sum1 += __shfl_xor_sync(0xffffffffu, sum1, 2);
        l0v = l0v * c0 + sum0;
        l1v = l1v * c1 + sum1;

        #pragma unroll
        for (int nt = 0; nt < 8; nt++) {
            o_acc[nt][0] *= c0; o_acc[nt][1] *= c0;
            o_acc[nt][2] *= c1; o_acc[nt][3] *= c1;
        }

        #pragma unroll
        for (int kc = 0; kc < 4; kc++) {
            const uint32_t ah0 = ph0[2 * kc],     ah1 = ph1[2 * kc];
            const uint32_t ah2 = ph0[2 * kc + 1], ah3 = ph1[2 * kc + 1];
            const uint32_t al0 = pl0[2 * kc],     al1 = pl1[2 * kc];
            const uint32_t al2 = pl0[2 * kc + 1], al3 = pl1[2 * kc + 1];
            #pragma unroll
            for (int nt = 0; nt < 8; nt++) {
                uint32_t bh0 = *(const uint32_t*)&Vh[(nt * 8 + g) * AQP + kc * 16 + 2 * t];
                uint32_t bh1 = *(const uint32_t*)&Vh[(nt * 8 + g) * AQP + kc * 16 + 2 * t + 8];
                uint32_t bl0 = *(const uint32_t*)&Vl[(nt * 8 + g) * AQP + kc * 16 + 2 * t];
                uint32_t bl1 = *(const uint32_t*)&Vl[(nt * 8 + g) * AQP + kc * 16 + 2 * t + 8];
                float* d = o_acc[nt];
                mma16816(d[0], d[1], d[2], d[3], ah0, ah1, ah2, ah3, bh0, bh1);
                mma16816(d[0], d[1], d[2], d[3], ah0, ah1, ah2, ah3, bl0, bl1);
                mma16816(d[0], d[1], d[2], d[3], al0, al1, al2, al3, bh0, bh1);
            }
        }
        __syncthreads();
    }

    const float inv0 = 1.f / l0v;
    const float inv1 = 1.f / l1v;
    #pragma unroll
    for (int nt = 0; nt < 8; nt++) {
        const int col = h * 64 + nt * 8 + 2 * t;
        float2 oa, ob;
        oa.x = fmaxf(o_acc[nt][0] * inv0, 0.f);
        oa.y = fmaxf(o_acc[nt][1] * inv0, 0.f);
        ob.x = fmaxf(o_acc[nt][2] * inv1, 0.f);
        ob.y = fmaxf(o_acc[nt][3] * inv1, 0.f);
        *(float2*)(out + ((size_t)bb * SS + r0g) * DD + col) = oa;
        *(float2*)(out + ((size_t)bb * SS + r1g) * DD + col) = ob;
    }
}

// ---------------------------------------------------------------------------
extern "C" void kernel_launch(void* const* d_in, const int* in_sizes, int n_in,
                              void* d_out, int out_size)
{
    const float* x   = (const float*)d_in[0];
    const float* adj = (const float*)d_in[1];
    const float* Wq  = (const float*)d_in[2];
    const float* bq  = (const float*)d_in[3];
    const float* Wk  = (const float*)d_in[4];
    const float* bk  = (const float*)d_in[5];
    const float* Wv  = (const float*)d_in[6];
    const float* bv  = (const float*)d_in[7];

    float* out     = (float*)d_out;
    float* out_adj = out + (size_t)BB * SS * DD;

    conv_x<<<(BB * SS * DD) / (256 * 4), 256>>>(x);
    conv_w<<<dim3(DD / 32, DD / 32, 3), dim3(32, 8)>>>(Wq, Wk, Wv);
    mask_pack<<<(BB * SS * (SS / 32)) / 256, 256>>>(adj, out_adj);

    cudaFuncSetAttribute(qkv_gemm_mma, cudaFuncAttributeMaxDynamicSharedMemorySize, GSMB);
    qkv_gemm_mma<<<dim3(DD / 128, (BB * SS) / 128, 3), 256, GSMB>>>(bq, bk, bv);
    v_conv<<<dim3(SS / 32, HD / 32, BB * HH), dim3(32, 8)>>>();

    const int attn_smem = (2 * T_ELEM + 8 * T_ELEM) * (int)sizeof(__nv_bfloat16);
    cudaFuncSetAttribute(attn_mma, cudaFuncAttributeMaxDynamicSharedMemorySize, attn_smem);
    attn_mma<<<dim3(SS / 64, HH, BB), 128, attn_smem>>>(out);
}

// round 9
// speedup vs baseline: 3.0692x; 1.1315x over previous
#include <cuda_runtime.h>
#include <cuda_bf16.h>
#include <cstdint>

#define BB 4
#define SS 1024
#define DD 1024
#define HH 16
#define HD 64
#define NEGV -10000000.0f

// ---------------------------------------------------------------------------
// Scratch (__device__ globals; no allocation allowed)
// ---------------------------------------------------------------------------
__device__ float g_v[BB*HH*SS*HD];                 // V fp32 (pre-transpose)
__device__ unsigned g_mask[BB*SS*(SS/32)];
__device__ __nv_bfloat16 g_xhi[BB*SS*DD];
__device__ __nv_bfloat16 g_xlo[BB*SS*DD];
__device__ __nv_bfloat16 g_whi[3][DD*DD];          // transposed: [n][k]
__device__ __nv_bfloat16 g_wlo[3][DD*DD];
__device__ __nv_bfloat16 g_qhi[BB*HH*SS*HD];       // [b,h,s,hd]
__device__ __nv_bfloat16 g_qlo[BB*HH*SS*HD];
__device__ __nv_bfloat16 g_khi[BB*HH*SS*HD];       // [b,h,s,hd]
__device__ __nv_bfloat16 g_klo[BB*HH*SS*HD];
__device__ __nv_bfloat16 g_vthi[BB*HH*HD*SS];      // [b,h,hd,s]  (transposed)
__device__ __nv_bfloat16 g_vtlo[BB*HH*HD*SS];

// ---------------------------------------------------------------------------
// PTX helpers (baseline PTX only — works on plain sm_103 target)
// ---------------------------------------------------------------------------
__device__ __forceinline__ void mma16816(
    float& d0, float& d1, float& d2, float& d3,
    uint32_t a0, uint32_t a1, uint32_t a2, uint32_t a3,
    uint32_t b0, uint32_t b1)
{
    asm volatile(
        "mma.sync.aligned.m16n8k16.row.col.f32.bf16.bf16.f32 "
        "{%0,%1,%2,%3}, {%4,%5,%6,%7}, {%8,%9}, {%0,%1,%2,%3};"
        : "+f"(d0), "+f"(d1), "+f"(d2), "+f"(d3)
        : "r"(a0), "r"(a1), "r"(a2), "r"(a3), "r"(b0), "r"(b1));
}

__device__ __forceinline__ void ldm_x4(
    uint32_t& r0, uint32_t& r1, uint32_t& r2, uint32_t& r3, uint32_t addr)
{
    asm volatile("ldmatrix.sync.aligned.m8n8.x4.shared.b16 {%0,%1,%2,%3}, [%4];"
        : "=r"(r0), "=r"(r1), "=r"(r2), "=r"(r3) : "r"(addr));
}

__device__ __forceinline__ uint32_t smem_u32(const void* p) {
    uint32_t a;
    asm("{ .reg .u64 t; cvta.to.shared.u64 t, %1; cvt.u32.u64 %0, t; }"
        : "=r"(a) : "l"(p));
    return a;
}

__device__ __forceinline__ void cp16(uint32_t dst, const void* src) {
    asm volatile("cp.async.cg.shared.global [%0], [%1], 16;" :: "r"(dst), "l"(src));
}
#define CP_COMMIT() asm volatile("cp.async.commit_group;" ::: "memory")

// ---------------------------------------------------------------------------
// Prep: split x into bf16 hi/lo
// ---------------------------------------------------------------------------
__global__ __launch_bounds__(256) void conv_x(const float* __restrict__ x)
{
    size_t i = ((size_t)blockIdx.x * 256 + threadIdx.x) * 4;
    float4 v = *(const float4*)(x + i);
    __nv_bfloat16 h0 = __float2bfloat16(v.x);
    __nv_bfloat16 h1 = __float2bfloat16(v.y);
    __nv_bfloat16 h2 = __float2bfloat16(v.z);
    __nv_bfloat16 h3 = __float2bfloat16(v.w);
    __nv_bfloat16 l0 = __float2bfloat16(v.x - __bfloat162float(h0));
    __nv_bfloat16 l1 = __float2bfloat16(v.y - __bfloat162float(h1));
    __nv_bfloat16 l2 = __float2bfloat16(v.z - __bfloat162float(h2));
    __nv_bfloat16 l3 = __float2bfloat16(v.w - __bfloat162float(h3));
    __nv_bfloat162 p;
    p.x = h0; p.y = h1; *(__nv_bfloat162*)(g_xhi + i)     = p;
    p.x = h2; p.y = h3; *(__nv_bfloat162*)(g_xhi + i + 2) = p;
    p.x = l0; p.y = l1; *(__nv_bfloat162*)(g_xlo + i)     = p;
    p.x = l2; p.y = l3; *(__nv_bfloat162*)(g_xlo + i + 2) = p;
}

// ---------------------------------------------------------------------------
// Prep: transpose W [K,N] -> Wt [N,K], split hi/lo
// ---------------------------------------------------------------------------
__global__ __launch_bounds__(256) void conv_w(
    const float* __restrict__ Wq, const float* __restrict__ Wk, const float* __restrict__ Wv)
{
    const int z = blockIdx.z;
    const float* W = z == 0 ? Wq : (z == 1 ? Wk : Wv);
    __shared__ float t[32][33];
    int tx = threadIdx.x, ty = threadIdx.y;
    int n0 = blockIdx.x * 32, k0 = blockIdx.y * 32;
    #pragma unroll
    for (int r = 0; r < 4; r++) {
        int k = k0 + ty + r * 8;
        t[ty + r * 8][tx] = W[(size_t)k * DD + n0 + tx];
    }
    __syncthreads();
    #pragma unroll
    for (int r = 0; r < 4; r++) {
        int nn = n0 + ty + r * 8;
        int kk = k0 + tx;
        float v = t[tx][ty + r * 8];
        __nv_bfloat16 hi = __float2bfloat16(v);
        __nv_bfloat16 lo = __float2bfloat16(v - __bfloat162float(hi));
        g_whi[z][(size_t)nn * DD + kk] = hi;
        g_wlo[z][(size_t)nn * DD + kk] = lo;
    }
}

// ---------------------------------------------------------------------------
// QKV GEMM via mma.sync + 3-stage cp.async pipeline (single barrier/chunk).
// CTA 128x128, 8 warps (2Mx4N), warp tile 64x32, K-chunk 32.
// SMEM arrays: 128 rows x 32 bf16 (64 B/row), XOR-swizzled 16B chunks:
//   chunk_phys = seg ^ ((row >> 1) & 3)   -> conflict-free ldmatrix phases.
// 3 stages x 4 arrays x 8 KB = 96 KB  -> 2 CTAs/SM.
// ---------------------------------------------------------------------------
#define GT2   (128 * 32)                 // elements per tile array
#define NSTG  3
#define GSMB  (NSTG * 4 * GT2 * 2)       // 98304 bytes

__device__ __forceinline__ uint32_t gsw(int row, int chunk) {
    return (uint32_t)(row * 64 + ((chunk ^ ((row >> 1) & 3)) << 4));
}

__global__ __launch_bounds__(256, 2) void qkv_gemm_mma(
    const float* __restrict__ bq, const float* __restrict__ bk, const float* __restrict__ bv)
{
    extern __shared__ __nv_bfloat16 gsm[];

    const int tid  = threadIdx.x;
    const int lane = tid & 31;
    const int wid  = tid >> 5;
    const int wm   = wid >> 2;
    const int wn   = wid & 3;
    const int z    = blockIdx.z;
    const int m0   = blockIdx.y * 128;
    const int n0   = blockIdx.x * 128;

    const __nv_bfloat16* __restrict__ gAh = g_xhi;
    const __nv_bfloat16* __restrict__ gAl = g_xlo;
    const __nv_bfloat16* __restrict__ gBh = g_whi[z];
    const __nv_bfloat16* __restrict__ gBl = g_wlo[z];
    const float* bias = z == 0 ? bq : (z == 1 ? bk : bv);

    const uint32_t sb = smem_u32(gsm);

    float acc[4][4][4];
    #pragma unroll
    for (int mt = 0; mt < 4; mt++)
        #pragma unroll
        for (int nt = 0; nt < 4; nt++)
            #pragma unroll
            for (int r = 0; r < 4; r++) acc[mt][nt][r] = 0.f;

    const int fr = lane >> 2;
    const int fc = (lane & 3) * 2;

    // ---- chunk issue: 4 arrays x 128 rows x 32 bf16 (4 swizzled 16B segs) --
    auto issue_chunk = [&](int c) {
        const uint32_t base = sb + (uint32_t)((c % NSTG) * 4 * GT2) * 2;
        const int k0 = c * 32;
        #pragma unroll
        for (int i = 0; i < 2; i++) {
            const int idx = tid + i * 256;       // 0..511
            const int row = idx >> 2;            // 0..127
            const int seg = idx & 3;             // 0..3
            const uint32_t doff = gsw(row, seg);
            const size_t ao = (size_t)(m0 + row) * DD + k0 + seg * 8;
            const size_t bo = (size_t)(n0 + row) * DD + k0 + seg * 8;
            cp16(base + 0u * GT2 * 2 + doff, gAh + ao);
            cp16(base + 1u * GT2 * 2 + doff, gAl + ao);
            cp16(base + 2u * GT2 * 2 + doff, gBh + bo);
            cp16(base + 3u * GT2 * 2 + doff, gBl + bo);
        }
        CP_COMMIT();
    };

    issue_chunk(0);
    issue_chunk(1);

    for (int c = 0; c < 32; c++) {
        if (c < 30) asm volatile("cp.async.wait_group 1;" ::: "memory");
        else        asm volatile("cp.async.wait_group 0;" ::: "memory");
        __syncthreads();

        const uint32_t sbase = sb + (uint32_t)((c % NSTG) * 4 * GT2) * 2;
        #pragma unroll
        for (int ks = 0; ks < 2; ks++) {
            const int kc = ks * 2;                    // base 16B-chunk of K half
            uint32_t ah[4][4], al[4][4], bh[4][2], bl[4][2];
            #pragma unroll
            for (int mt = 0; mt < 4; mt++) {
                const int row = wm * 64 + mt * 16 + (lane & 15);
                const uint32_t aoff = gsw(row, kc + (lane >> 4));
                ldm_x4(ah[mt][0], ah[mt][1], ah[mt][2], ah[mt][3],
                       sbase + 0u * GT2 * 2 + aoff);
                ldm_x4(al[mt][0], al[mt][1], al[mt][2], al[mt][3],
                       sbase + 1u * GT2 * 2 + aoff);
            }
            #pragma unroll
            for (int np = 0; np < 2; np++) {
                const int row = wn * 32 + np * 16 + (lane & 7) + ((lane >> 4) << 3);
                const uint32_t boff = gsw(row, kc + ((lane >> 3) & 1));
                ldm_x4(bh[np * 2][0], bh[np * 2][1], bh[np * 2 + 1][0], bh[np * 2 + 1][1],
                       sbase + 2u * GT2 * 2 + boff);
                ldm_x4(bl[np * 2][0], bl[np * 2][1], bl[np * 2 + 1][0], bl[np * 2 + 1][1],
                       sbase + 3u * GT2 * 2 + boff);
            }
            // term-major: consecutive HMMAs hit different accumulators
            #pragma unroll
            for (int mt = 0; mt < 4; mt++)
                #pragma unroll
                for (int nt = 0; nt < 4; nt++)
                    mma16816(acc[mt][nt][0], acc[mt][nt][1], acc[mt][nt][2], acc[mt][nt][3],
                             ah[mt][0], ah[mt][1], ah[mt][2], ah[mt][3],
                             bh[nt][0], bh[nt][1]);
            #pragma unroll
            for (int mt = 0; mt < 4; mt++)
                #pragma unroll
                for (int nt = 0; nt < 4; nt++)
                    mma16816(acc[mt][nt][0], acc[mt][nt][1], acc[mt][nt][2], acc[mt][nt][3],
                             ah[mt][0], ah[mt][1], ah[mt][2], ah[mt][3],
                             bl[nt][0], bl[nt][1]);
            #pragma unroll
            for (int mt = 0; mt < 4; mt++)
                #pragma unroll
                for (int nt = 0; nt < 4; nt++)
                    mma16816(acc[mt][nt][0], acc[mt][nt][1], acc[mt][nt][2], acc[mt][nt][3],
                             al[mt][0], al[mt][1], al[mt][2], al[mt][3],
                             bh[nt][0], bh[nt][1]);
        }

        // Buffer (c+2)%3 == (c-1)%3: its readers (compute c-1) finished
        // before this iteration's barrier -> safe without a second barrier.
        if (c + 2 < 32) issue_chunk(c + 2);
    }

    __nv_bfloat16* ohi = z == 0 ? g_qhi : g_khi;
    __nv_bfloat16* olo = z == 0 ? g_qlo : g_klo;

    #pragma unroll
    for (int nt = 0; nt < 4; nt++) {
        const int n = n0 + wn * 32 + nt * 8 + fc;
        const int h = n >> 6;
        const int hd = n & 63;
        const float bv0 = bias[n];
        const float bv1 = bias[n + 1];
        #pragma unroll
        for (int mt = 0; mt < 4; mt++) {
            #pragma unroll
            for (int half = 0; half < 2; half++) {
                const int m = m0 + wm * 64 + mt * 16 + fr + half * 8;
                const int bb = m >> 10;
                const int s = m & 1023;
                float v0 = acc[mt][nt][half * 2 + 0] + bv0;
                float v1 = acc[mt][nt][half * 2 + 1] + bv1;
                size_t idx = ((size_t)(bb * HH + h) * SS + s) * HD + hd;
                if (z < 2) {
                    __nv_bfloat162 hv = __floats2bfloat162_rn(v0, v1);
                    __nv_bfloat162 lv = __floats2bfloat162_rn(
                        v0 - __bfloat162float(hv.x), v1 - __bfloat162float(hv.y));
                    *(__nv_bfloat162*)(ohi + idx) = hv;
                    *(__nv_bfloat162*)(olo + idx) = lv;
                } else {
                    float2 o; o.x = v0; o.y = v1;
                    *(float2*)(g_v + idx) = o;
                }
            }
        }
    }
}

// ---------------------------------------------------------------------------
// V: transpose [b,h,s,hd] f32 -> [b,h,hd,s] bf16 hi/lo
// ---------------------------------------------------------------------------
__global__ __launch_bounds__(256) void v_conv()
{
    __shared__ float t[32][33];
    const int bh = blockIdx.z;
    const int s0 = blockIdx.x * 32;
    const int hd0 = blockIdx.y * 32;
    const int tx = threadIdx.x, ty = threadIdx.y;
    #pragma unroll
    for (int r = 0; r < 4; r++) {
        int s = s0 + ty + r * 8;
        t[ty + r * 8][tx] = g_v[((size_t)bh * SS + s) * HD + hd0 + tx];
    }
    __syncthreads();
    #pragma unroll
    for (int r = 0; r < 4; r++) {
        int hd = hd0 + ty + r * 8;
        int s = s0 + tx;
        float v = t[tx][ty + r * 8];
        __nv_bfloat16 hi = __float2bfloat16(v);
        __nv_bfloat16 lo = __float2bfloat16(v - __bfloat162float(hi));
        g_vthi[((size_t)bh * HD + hd) * SS + s] = hi;
        g_vtlo[((size_t)bh * HD + hd) * SS + s] = lo;
    }
}

// ---------------------------------------------------------------------------
// Pack adj into 1-bit mask and copy adj to second output region.
// ---------------------------------------------------------------------------
__global__ __launch_bounds__(256) void mask_pack(
    const float* __restrict__ adj, float* __restrict__ adj_out)
{
    int w = blockIdx.x * blockDim.x + threadIdx.x;
    const float4* a4 = (const float4*)adj;
    float4* o4 = (float4*)adj_out;
    unsigned bits = 0;
    #pragma unroll
    for (int i = 0; i < 8; i++) {
        float4 v = a4[(size_t)w * 8 + i];
        o4[(size_t)w * 8 + i] = v;
        bits |= (v.x >= 0.5f ? 1u : 0u) << (i * 4 + 0);
        bits |= (v.y >= 0.5f ? 1u : 0u) << (i * 4 + 1);
        bits |= (v.z >= 0.5f ? 1u : 0u) << (i * 4 + 2);
        bits |= (v.w >= 0.5f ? 1u : 0u) << (i * 4 + 3);
    }
    g_mask[w] = bits;
}

// ---------------------------------------------------------------------------
// Flash attention via mma.sync: q-tile 64, 128 threads, cp.async DB.
// ---------------------------------------------------------------------------
#define AQP 72
#define T_ELEM (64 * AQP)

__global__ __launch_bounds__(128) void attn_mma(float* __restrict__ out)
{
    extern __shared__ __nv_bfloat16 smp[];
    __nv_bfloat16* Qh = smp;
    __nv_bfloat16* Ql = Qh + T_ELEM;
    __nv_bfloat16* KV = Ql + T_ELEM;

    const int tid  = threadIdx.x;
    const int lane = tid & 31;
    const int warp = tid >> 5;
    const int g    = lane >> 2;
    const int t    = lane & 3;
    const int q0   = blockIdx.x * 64;
    const int h    = blockIdx.y;
    const int bb   = blockIdx.z;
    const int wq0  = warp * 16;

    const size_t bhs = ((size_t)(bb * HH + h)) * SS;
    const __nv_bfloat16* gqh = g_qhi + (bhs + q0) * HD;
    const __nv_bfloat16* gql = g_qlo + (bhs + q0) * HD;
    const __nv_bfloat16* gkh = g_khi + bhs * HD;
    const __nv_bfloat16* gkl = g_klo + bhs * HD;
    const __nv_bfloat16* gvh = g_vthi + ((size_t)(bb * HH + h)) * HD * SS;
    const __nv_bfloat16* gvl = g_vtlo + ((size_t)(bb * HH + h)) * HD * SS;

    const uint32_t sQh = smem_u32(Qh);
    const uint32_t sQl = smem_u32(Ql);
    const uint32_t sKV = smem_u32(KV);

    {
        const int row = tid >> 3;
        const int seg = tid & 7;
        #pragma unroll
        for (int j = 0; j < 4; j++) {
            int r = row + j * 16;
            uint32_t doff = (uint32_t)(r * AQP + seg * 8) * 2;
            cp16(sQh + doff, gqh + (size_t)r * HD + seg * 8);
            cp16(sQl + doff, gql + (size_t)r * HD + seg * 8);
        }
        #pragma unroll
        for (int j = 0; j < 4; j++) {
            int r = row + j * 16;
            uint32_t doff = (uint32_t)(r * AQP + seg * 8) * 2;
            cp16(sKV + 0 * T_ELEM * 2 + doff, gkh + (size_t)r * HD + seg * 8);
            cp16(sKV + 1 * T_ELEM * 2 + doff, gkl + (size_t)r * HD + seg * 8);
            cp16(sKV + 2 * T_ELEM * 2 + doff, gvh + (size_t)r * SS + seg * 8);
            cp16(sKV + 3 * T_ELEM * 2 + doff, gvl + (size_t)r * SS + seg * 8);
        }
        CP_COMMIT();
    }

    float o_acc[8][4];
    #pragma unroll
    for (int nt = 0; nt < 8; nt++)
        #pragma unroll
        for (int e = 0; e < 4; e++) o_acc[nt][e] = 0.f;
    float m0v = -1e30f, m1v = -1e30f, l0v = 0.f, l1v = 0.f;

    const unsigned* mrow = g_mask + (size_t)bb * SS * (SS / 32);
    const int r0g = q0 + wq0 + g;
    const int r1g = r0g + 8;

    for (int kt = 0; kt < 16; kt++) {
        const int cur = kt & 1;
        if (kt + 1 < 16) {
            const int nxt = (kt + 1) & 1;
            const uint32_t base = sKV + (uint32_t)(nxt * 4 * T_ELEM) * 2;
            const int row = tid >> 3;
            const int seg = tid & 7;
            const size_t koff = (size_t)(kt + 1) * 64;
            #pragma unroll
            for (int j = 0; j < 4; j++) {
                int r = row + j * 16;
                uint32_t doff = (uint32_t)(r * AQP + seg * 8) * 2;
                cp16(base + 0 * T_ELEM * 2 + doff, gkh + (koff + r) * HD + seg * 8);
                cp16(base + 1 * T_ELEM * 2 + doff, gkl + (koff + r) * HD + seg * 8);
                cp16(base + 2 * T_ELEM * 2 + doff, gvh + (size_t)r * SS + koff + seg * 8);
                cp16(base + 3 * T_ELEM * 2 + doff, gvl + (size_t)r * SS + koff + seg * 8);
            }
            CP_COMMIT();
            asm volatile("cp.async.wait_group 1;" ::: "memory");
        } else {
            asm volatile("cp.async.wait_group 0;" ::: "memory");
        }
        __syncthreads();

        const __nv_bfloat16* Kh = KV + (cur * 4 + 0) * T_ELEM;
        const __nv_bfloat16* Kl = KV + (cur * 4 + 1) * T_ELEM;
        const __nv_bfloat16* Vh = KV + (cur * 4 + 2) * T_ELEM;
        const __nv_bfloat16* Vl = KV + (cur * 4 + 3) * T_ELEM;

        float sf[8][4];
        #pragma unroll
        for (int nt = 0; nt < 8; nt++)
            #pragma unroll
            for (int e = 0; e < 4; e++) sf[nt][e] = 0.f;

        #pragma unroll
        for (int kk = 0; kk < 4; kk++) {
            const int kb = kk * 16;
            uint32_t qah[4], qal[4];
            qah[0] = *(const uint32_t*)&Qh[(wq0 + g) * AQP + kb + 2 * t];
            qah[1] = *(const uint32_t*)&Qh[(wq0 + g + 8) * AQP + kb + 2 * t];
            qah[2] = *(const uint32_t*)&Qh[(wq0 + g) * AQP + kb + 2 * t + 8];
            qah[3] = *(const uint32_t*)&Qh[(wq0 + g + 8) * AQP + kb + 2 * t + 8];
            qal[0] = *(const uint32_t*)&Ql[(wq0 + g) * AQP + kb + 2 * t];
            qal[1] = *(const uint32_t*)&Ql[(wq0 + g + 8) * AQP + kb + 2 * t];
            qal[2] = *(const uint32_t*)&Ql[(wq0 + g) * AQP + kb + 2 * t + 8];
            qal[3] = *(const uint32_t*)&Ql[(wq0 + g + 8) * AQP + kb + 2 * t + 8];
            #pragma unroll
            for (int nt = 0; nt < 8; nt++) {
                uint32_t bh0 = *(const uint32_t*)&Kh[(nt * 8 + g) * AQP + kb + 2 * t];
                uint32_t bh1 = *(const uint32_t*)&Kh[(nt * 8 + g) * AQP + kb + 2 * t + 8];
                uint32_t bl0 = *(const uint32_t*)&Kl[(nt * 8 + g) * AQP + kb + 2 * t];
                uint32_t bl1 = *(const uint32_t*)&Kl[(nt * 8 + g) * AQP + kb + 2 * t + 8];
                float* d = sf[nt];
                mma16816(d[0], d[1], d[2], d[3], qah[0], qah[1], qah[2], qah[3], bh0, bh1);
                mma16816(d[0], d[1], d[2], d[3], qah[0], qah[1], qah[2], qah[3], bl0, bl1);
                mma16816(d[0], d[1], d[2], d[3], qal[0], qal[1], qal[2], qal[3], bh0, bh1);
            }
        }

        const unsigned w0 = mrow[(size_t)r0g * 32 + kt * 2];
        const unsigned w1 = mrow[(size_t)r0g * 32 + kt * 2 + 1];
        const unsigned w2 = mrow[(size_t)r1g * 32 + kt * 2];
        const unsigned w3 = mrow[(size_t)r1g * 32 + kt * 2 + 1];

        float mx0 = -1e30f, mx1 = -1e30f;
        #pragma unroll
        for (int nt = 0; nt < 8; nt++) {
            const unsigned wa = nt < 4 ? w0 : w1;
            const unsigned wb = nt < 4 ? w2 : w3;
            const int sh = (nt & 3) * 8 + 2 * t;
            float v0 = sf[nt][0] * 0.125f + (((wa >> sh) & 1u) ? 0.f : NEGV);
            float v1 = sf[nt][1] * 0.125f + (((wa >> (sh + 1)) & 1u) ? 0.f : NEGV);
            float v2 = sf[nt][2] * 0.125f + (((wb >> sh) & 1u) ? 0.f : NEGV);
            float v3 = sf[nt][3] * 0.125f + (((wb >> (sh + 1)) & 1u) ? 0.f : NEGV);
            sf[nt][0] = v0; sf[nt][1] = v1; sf[nt][2] = v2; sf[nt][3] = v3;
            mx0 = fmaxf(mx0, fmaxf(v0, v1));
            mx1 = fmaxf(mx1, fmaxf(v2, v3));
        }
        mx0 = fmaxf(mx0, __shfl_xor_sync(0xffffffffu, mx0, 1));
        mx0 = fmaxf(mx0, __shfl_xor_sync(0xffffffffu, mx0, 2));
        mx1 = fmaxf(mx1, __shfl_xor_sync(0xffffffffu, mx1, 1));
        mx1 = fmaxf(mx1, __shfl_xor_sync(0xffffffffu, mx1, 2));

        const float mn0 = fmaxf(m0v, mx0);
        const float mn1 = fmaxf(m1v, mx1);
        const float c0 = __expf(m0v - mn0);
        const float c1 = __expf(m1v - mn1);
        m0v = mn0; m1v = mn1;

        float sum0 = 0.f, sum1 = 0.f;
        uint32_t ph0[8], pl0[8], ph1[8], pl1[8];
        #pragma unroll
        for (int nt = 0; nt < 8; nt++) {
            float p00 = __expf(sf[nt][0] - mn0);
            float p01 = __expf(sf[nt][1] - mn0);
            float p10 = __expf(sf[nt][2] - mn1);
            float p11 = __expf(sf[nt][3] - mn1);
            sum0 += p00 + p01;
            sum1 += p10 + p11;
            __nv_bfloat162 hv0 = __floats2bfloat162_rn(p00, p01);
            __nv_bfloat162 lv0 = __floats2bfloat162_rn(
                p00 - __bfloat162float(hv0.x), p01 - __bfloat162float(hv0.y));
            __nv_bfloat162 hv1 = __floats2bfloat162_rn(p10, p11);
            __nv_bfloat162 lv1 = __floats2bfloat162_rn(
                p10 - __bfloat162float(hv1.x), p11 - __bfloat162float(hv1.y));
            ph0[nt] = *(uint32_t*)&hv0; pl0[nt] = *(uint32_t*)&lv0;
            ph1[nt] = *(uint32_t*)&hv1; pl1[nt] = *(uint32_t*)&lv1;
        }
        sum0 += __shfl_xor_sync(0xffffffffu, sum0, 1);
        sum0 += __shfl_xor_sync(0xffffffffu, sum0, 2);
        sum1 += __shfl_xor_sync(0xffffffffu, sum1, 1);
        sum1 += __shfl_xor_sync(0xffffffffu, sum1, 2);
        l0v = l0v * c0 + sum0;
        l1v = l1v * c1 + sum1;

        #pragma unroll
        for (int nt = 0; nt < 8; nt++) {
            o_acc[nt][0] *= c0; o_acc[nt][1] *= c0;
            o_acc[nt][2] *= c1; o_acc[nt][3] *= c1;
        }

        #pragma unroll
        for (int kc = 0; kc < 4; kc++) {
            const uint32_t ah0 = ph0[2 * kc],     ah1 = ph1[2 * kc];
            const uint32_t ah2 = ph0[2 * kc + 1], ah3 = ph1[2 * kc + 1];
            const uint32_t al0 = pl0[2 * kc],     al1 = pl1[2 * kc];
            const uint32_t al2 = pl0[2 * kc + 1], al3 = pl1[2 * kc + 1];
            #pragma unroll
            for (int nt = 0; nt < 8; nt++) {
                uint32_t bh0 = *(const uint32_t*)&Vh[(nt * 8 + g) * AQP + kc * 16 + 2 * t];
                uint32_t bh1 = *(const uint32_t*)&Vh[(nt * 8 + g) * AQP + kc * 16 + 2 * t + 8];
                uint32_t bl0 = *(const uint32_t*)&Vl[(nt * 8 + g) * AQP + kc * 16 + 2 * t];
                uint32_t bl1 = *(const uint32_t*)&Vl[(nt * 8 + g) * AQP + kc * 16 + 2 * t + 8];
                float* d = o_acc[nt];
                mma16816(d[0], d[1], d[2], d[3], ah0, ah1, ah2, ah3, bh0, bh1);
                mma16816(d[0], d[1], d[2], d[3], ah0, ah1, ah2, ah3, bl0, bl1);
                mma16816(d[0], d[1], d[2], d[3], al0, al1, al2, al3, bh0, bh1);
            }
        }
        __syncthreads();
    }

    const float inv0 = 1.f / l0v;
    const float inv1 = 1.f / l1v;
    #pragma unroll
    for (int nt = 0; nt < 8; nt++) {
        const int col = h * 64 + nt * 8 + 2 * t;
        float2 oa, ob;
        oa.x = fmaxf(o_acc[nt][0] * inv0, 0.f);
        oa.y = fmaxf(o_acc[nt][1] * inv0, 0.f);
        ob.x = fmaxf(o_acc[nt][2] * inv1, 0.f);
        ob.y = fmaxf(o_acc[nt][3] * inv1, 0.f);
        *(float2*)(out + ((size_t)bb * SS + r0g) * DD + col) = oa;
        *(float2*)(out + ((size_t)bb * SS + r1g) * DD + col) = ob;
    }
}

// ---------------------------------------------------------------------------
extern "C" void kernel_launch(void* const* d_in, const int* in_sizes, int n_in,
                              void* d_out, int out_size)
{
    const float* x   = (const float*)d_in[0];
    const float* adj = (const float*)d_in[1];
    const float* Wq  = (const float*)d_in[2];
    const float* bq  = (const float*)d_in[3];
    const float* Wk  = (const float*)d_in[4];
    const float* bk  = (const float*)d_in[5];
    const float* Wv  = (const float*)d_in[6];
    const float* bv  = (const float*)d_in[7];

    float* out     = (float*)d_out;
    float* out_adj = out + (size_t)BB * SS * DD;

    conv_x<<<(BB * SS * DD) / (256 * 4), 256>>>(x);
    conv_w<<<dim3(DD / 32, DD / 32, 3), dim3(32, 8)>>>(Wq, Wk, Wv);
    mask_pack<<<(BB * SS * (SS / 32)) / 256, 256>>>(adj, out_adj);

    cudaFuncSetAttribute(qkv_gemm_mma, cudaFuncAttributeMaxDynamicSharedMemorySize, GSMB);
    qkv_gemm_mma<<<dim3(DD / 128, (BB * SS) / 128, 3), 256, GSMB>>>(bq, bk, bv);
    v_conv<<<dim3(SS / 32, HD / 32, BB * HH), dim3(32, 8)>>>();

    const int attn_smem = (2 * T_ELEM + 8 * T_ELEM) * (int)sizeof(__nv_bfloat16);
    cudaFuncSetAttribute(attn_mma, cudaFuncAttributeMaxDynamicSharedMemorySize, attn_smem);
    attn_mma<<<dim3(SS / 64, HH, BB), 128, attn_smem>>>(out);
}